// round 11
// baseline (speedup 1.0000x reference)
#include <cuda_runtime.h>

#define N0MAX 500000
#define WMAX  15680          // >= gdiv(N0MAX, 32)
#define EPS   1e-4f

// ---------------------------------------------------------------------------
// Scratch (device globals — no runtime allocation allowed)
// ---------------------------------------------------------------------------
__device__ float g_X0[N0MAX * 16];
__device__ float g_X1[N0MAX * 16];
__device__ float g_X2[N0MAX * 16];
__device__ float g_T1[N0MAX * 16];
__device__ float g_T2[N0MAX * 16];
// flat pair lists per rulebook; pair = ((k<<20)|out_i, in_idx)
__device__ int2     g_pairs[(size_t)97 * N0MAX];
__device__ int      g_wcnt[160 * WMAX];   // per-(rb k, warp) counts -> bases
__device__ int      g_cnt[160];           // per-(rb k) totals
__device__ int      g_kbase[160];         // per-(rb k) flat base; [cbase+K]=total
__device__ float    g_stats[96];          // sum[0..47], sumsq[48..95]
__device__ float    g_scale[48];
__device__ float    g_shift[48];
__device__ unsigned g_ticket;
__device__ unsigned g_bar;                // co-resident barrier arrivals (self-reset)
__device__ unsigned g_epoch;              // monotonic epoch

#define RB0_P ((size_t)0)
#define RB1_P ((size_t)27 * N0MAX)
#define RB2_P ((size_t)54 * N0MAX)
#define RB3_P ((size_t)81 * N0MAX)
#define RB4_P ((size_t)89 * N0MAX)

// ---------------------------------------------------------------------------
// f32x2 packed-math helpers (sm_103a FFMA2 — only reachable via PTX)
// ---------------------------------------------------------------------------
__device__ __forceinline__ unsigned long long fma2(unsigned long long a,
                                                   unsigned long long b,
                                                   unsigned long long c) {
    unsigned long long d;
    asm("fma.rn.f32x2 %0, %1, %2, %3;" : "=l"(d) : "l"(a), "l"(b), "l"(c));
    return d;
}
__device__ __forceinline__ unsigned long long dup2(float v) {
    unsigned long long d;
    asm("mov.b64 %0, {%1, %1};" : "=l"(d) : "f"(v));
    return d;
}
__device__ __forceinline__ float2 up2(unsigned long long v) {
    float2 f;
    asm("mov.b64 {%0, %1}, %2;" : "=f"(f.x), "=f"(f.y) : "l"(v));
    return f;
}
__device__ __forceinline__ void red4(float* p, float4 v) {
    asm volatile("red.global.add.v4.f32 [%0], {%1, %2, %3, %4};"
                 :: "l"(p), "f"(v.x), "f"(v.y), "f"(v.z), "f"(v.w) : "memory");
}

#define JSTEP2(Wk, jj, yv, a0, a1, a2, a3, a4, a5, a6, a7) { \
    unsigned long long yy = dup2(yv); \
    ulonglong2 p0 = (Wk)[4*(jj)+0], p1 = (Wk)[4*(jj)+1]; \
    ulonglong2 p2 = (Wk)[4*(jj)+2], p3 = (Wk)[4*(jj)+3]; \
    a0 = fma2(yy, p0.x, a0); a1 = fma2(yy, p0.y, a1); \
    a2 = fma2(yy, p1.x, a2); a3 = fma2(yy, p1.y, a3); \
    a4 = fma2(yy, p2.x, a4); a5 = fma2(yy, p2.y, a5); \
    a6 = fma2(yy, p3.x, a6); a7 = fma2(yy, p3.y, a7); }

#define JSTEP16(Wk, y0, y1, y2, y3, a0, a1, a2, a3, a4, a5, a6, a7) \
    JSTEP2(Wk, 0,  y0.x, a0,a1,a2,a3,a4,a5,a6,a7) \
    JSTEP2(Wk, 1,  y0.y, a0,a1,a2,a3,a4,a5,a6,a7) \
    JSTEP2(Wk, 2,  y0.z, a0,a1,a2,a3,a4,a5,a6,a7) \
    JSTEP2(Wk, 3,  y0.w, a0,a1,a2,a3,a4,a5,a6,a7) \
    JSTEP2(Wk, 4,  y1.x, a0,a1,a2,a3,a4,a5,a6,a7) \
    JSTEP2(Wk, 5,  y1.y, a0,a1,a2,a3,a4,a5,a6,a7) \
    JSTEP2(Wk, 6,  y1.z, a0,a1,a2,a3,a4,a5,a6,a7) \
    JSTEP2(Wk, 7,  y1.w, a0,a1,a2,a3,a4,a5,a6,a7) \
    JSTEP2(Wk, 8,  y2.x, a0,a1,a2,a3,a4,a5,a6,a7) \
    JSTEP2(Wk, 9,  y2.y, a0,a1,a2,a3,a4,a5,a6,a7) \
    JSTEP2(Wk, 10, y2.z, a0,a1,a2,a3,a4,a5,a6,a7) \
    JSTEP2(Wk, 11, y2.w, a0,a1,a2,a3,a4,a5,a6,a7) \
    JSTEP2(Wk, 12, y3.x, a0,a1,a2,a3,a4,a5,a6,a7) \
    JSTEP2(Wk, 13, y3.y, a0,a1,a2,a3,a4,a5,a6,a7) \
    JSTEP2(Wk, 14, y3.z, a0,a1,a2,a3,a4,a5,a6,a7) \
    JSTEP2(Wk, 15, y3.w, a0,a1,a2,a3,a4,a5,a6,a7)

// ---------------------------------------------------------------------------
__global__ void zero_misc_kernel() {
    int t = threadIdx.x;
    if (t < 96) g_stats[t] = 0.0f;
    if (t == 0) g_ticket = 0u;
}

// ---------------------------------------------------------------------------
// Co-resident grid barrier with fused BN finalize by the last-arriving block.
// Requires grid fully resident (enforced by __launch_bounds__ + grid cap).
// ---------------------------------------------------------------------------
__device__ __forceinline__ void grid_sync_fin(unsigned target,
                                              const float* gg, const float* bb,
                                              float invN, int Cfin) {
    __syncthreads();
    if (threadIdx.x == 0) {
        __threadfence();
        unsigned a = atomicAdd(&g_bar, 1u);
        if (a == gridDim.x - 1u) {
            for (int c = 0; c < Cfin; c++) {
                float m = __ldcg(&g_stats[c]) * invN;
                float var = __ldcg(&g_stats[48 + c]) * invN - m * m;
                float sc = __ldg(gg + c) * rsqrtf(var + EPS);
                g_scale[c] = sc;
                g_shift[c] = __ldg(bb + c) - m * sc;
                g_stats[c] = 0.0f;
                g_stats[48 + c] = 0.0f;
            }
            g_bar = 0u;
            __threadfence();
            atomicAdd(&g_epoch, 1u);
        } else {
            while ((int)(*(volatile unsigned*)&g_epoch - target) < 0)
                __nanosleep(64);
            __threadfence();
        }
    }
    __syncthreads();
}

// block-level stats flush into g_stats[off..]
__device__ __forceinline__ void stats_flush(float* s, float* q, int off,
                                            float (*ws)[32]) {
#pragma unroll
    for (int c = 0; c < 16; c++) {
#pragma unroll
        for (int o = 16; o > 0; o >>= 1) {
            s[c] += __shfl_xor_sync(0xffffffffu, s[c], o);
            q[c] += __shfl_xor_sync(0xffffffffu, q[c], o);
        }
    }
    int lane = threadIdx.x & 31, wid = threadIdx.x >> 5;
    if (lane == 0) {
#pragma unroll
        for (int c = 0; c < 16; c++) { ws[wid][c] = s[c]; ws[wid][16 + c] = q[c]; }
    }
    __syncthreads();
    if (threadIdx.x < 32) {
        float v = 0.0f;
        for (int w = 0; w < 8; w++) v += ws[w][threadIdx.x];
        int t = threadIdx.x;
        atomicAdd(&g_stats[(t < 16) ? (off + t) : (48 + off + t - 16)], v);
    }
    __syncthreads();
}

// ---------------------------------------------------------------------------
// Compaction phase 1: per-(k, warp) active counts. Preloaded nbr reads for
// MLP (the old #pragma unroll 1 form was MLP=1 latency-bound @30us/pass).
// k==13 (self) excluded for K=27 rulebooks.
// ---------------------------------------------------------------------------
template <int K>
__device__ __forceinline__ void count_dev(const int* __restrict__ nbr,
                                          int Nout, int Nin, int cbase, int lb) {
    int i = lb * 256 + threadIdx.x;
    bool inb = i < Nout;
    int lane = threadIdx.x & 31;
    int w = i >> 5;
    int idx[K];
#pragma unroll
    for (int k = 0; k < K; k++)
        idx[k] = inb ? __ldg(nbr + (size_t)k * Nout + i) : Nin;
#pragma unroll
    for (int k = 0; k < K; k++) {
        if (K == 27 && k == 13) continue;
        unsigned m = __ballot_sync(0xffffffffu, idx[k] < Nin);
        if (lane == 0) g_wcnt[(size_t)(cbase + k) * WMAX + w] = __popc(m);
    }
}

__global__ void count_all_kernel(const int* nbr0, const int* nbr1,
                                 const int* nbr2, const int* d01,
                                 const int* d12, int N0, int N1, int N2,
                                 int B0, int B01, int B012, int B0123) {
    int b = blockIdx.x;
    if (b < B0)           count_dev<27>(nbr0, N0, N0, 0,   b);
    else if (b < B01)     count_dev<27>(nbr1, N1, N1, 32,  b - B0);
    else if (b < B012)    count_dev<27>(nbr2, N2, N2, 64,  b - B01);
    else if (b < B0123)   count_dev<8> (d01,  N1, N0, 96,  b - B012);
    else                  count_dev<8> (d12,  N2, N1, 128, b - B0123);
}

// ---------------------------------------------------------------------------
// Compaction phase 2: exclusive scan per (rb, k) row; one block per row.
// ---------------------------------------------------------------------------
__global__ void scan_rows_kernel(int nw0, int nw1, int nw2, int nw3, int nw4) {
    int b = blockIdx.x;
    int row, nw;
    if (b < 27)      { row = b;            nw = nw0; }
    else if (b < 54) { row = 32 + b - 27;  nw = nw1; }
    else if (b < 81) { row = 64 + b - 54;  nw = nw2; }
    else if (b < 89) { row = 96 + b - 81;  nw = nw3; }
    else             { row = 128 + b - 89; nw = nw4; }
    if (row == 13 || row == 45 || row == 77) {
        if (threadIdx.x == 0) g_cnt[row] = 0;
        return;
    }
    int* p = g_wcnt + (size_t)row * WMAX;
    int t = threadIdx.x, lane = t & 31, wid = t >> 5;
    __shared__ int wtot[8];
    __shared__ int carry;
    if (t == 0) carry = 0;
    __syncthreads();
    for (int base = 0; base < nw; base += 256) {
        int v = (base + t < nw) ? p[base + t] : 0;
        int x = v;
#pragma unroll
        for (int off = 1; off < 32; off <<= 1) {
            int yv = __shfl_up_sync(0xffffffffu, x, off);
            if (lane >= off) x += yv;
        }
        if (lane == 31) wtot[wid] = x;
        __syncthreads();
        int wofs = 0;
#pragma unroll
        for (int w2 = 0; w2 < 8; w2++) wofs += (w2 < wid) ? wtot[w2] : 0;
        if (base + t < nw) p[base + t] = x - v + wofs + carry;
        __syncthreads();
        if (t == 0) {
            int s = 0;
#pragma unroll
            for (int w2 = 0; w2 < 8; w2++) s += wtot[w2];
            carry += s;
        }
        __syncthreads();
    }
    if (t == 0) g_cnt[row] = carry;
}

// Per-rb exclusive scan over k -> flat bucket bases + totals (1 warp per rb).
__global__ void bucket_base_kernel() {
    int wid = threadIdx.x >> 5;
    int lane = threadIdx.x & 31;
    if (wid >= 5) return;
    const int cb[5] = {0, 32, 64, 96, 128};
    const int kk[5] = {27, 27, 27, 8, 8};
    int K = kk[wid], base = cb[wid];
    int v = (lane < K) ? __ldg(&g_cnt[base + lane]) : 0;
    int x = v;
#pragma unroll
    for (int off = 1; off < 32; off <<= 1) {
        int yv = __shfl_up_sync(0xffffffffu, x, off);
        if (lane >= off) x += yv;
    }
    if (lane < K) g_kbase[base + lane] = x - v;
    int tot = __shfl_sync(0xffffffffu, x, K - 1);
    if (lane == K) g_kbase[base + K] = tot;
}

// ---------------------------------------------------------------------------
// Compaction phase 3: preloaded fill; write pairs at flat slots; skip k==13.
// ---------------------------------------------------------------------------
template <int K>
__device__ __forceinline__ void fill_dev(const int* __restrict__ nbr,
                                         int Nout, int Nin, int cbase,
                                         size_t pbase, int lb) {
    int i = lb * 256 + threadIdx.x;
    bool inb = i < Nout;
    int lane = threadIdx.x & 31;
    int w = i >> 5;
    unsigned lt = (1u << lane) - 1u;
    int idx[K];
#pragma unroll
    for (int k = 0; k < K; k++)
        idx[k] = inb ? __ldg(nbr + (size_t)k * Nout + i) : Nin;
#pragma unroll
    for (int k = 0; k < K; k++) {
        if (K == 27 && k == 13) continue;
        bool act = idx[k] < Nin;
        unsigned m = __ballot_sync(0xffffffffu, act);
        if (!m) continue;
        int base = __ldg(&g_kbase[cbase + k]) +
                   __ldg(&g_wcnt[(size_t)(cbase + k) * WMAX + w]);
        if (act)
            g_pairs[pbase + base + __popc(m & lt)] =
                make_int2((k << 20) | i, idx[k]);
    }
}

__global__ void fill_all_kernel(const int* nbr0, const int* nbr1,
                                const int* nbr2, const int* d01,
                                const int* d12, int N0, int N1, int N2,
                                int B0, int B01, int B012, int B0123) {
    int b = blockIdx.x;
    if (b < B0)           fill_dev<27>(nbr0, N0, N0, 0,   RB0_P, b);
    else if (b < B01)     fill_dev<27>(nbr1, N1, N1, 32,  RB1_P, b - B0);
    else if (b < B012)    fill_dev<27>(nbr2, N2, N2, 64,  RB2_P, b - B01);
    else if (b < B0123)   fill_dev<8> (d01,  N1, N0, 96,  RB3_P, b - B012);
    else                  fill_dev<8> (d12,  N2, N1, 128, RB4_P, b - B0123);
}

// ---------------------------------------------------------------------------
// Pair-parallel sparse conv 16->16 (non-self), FFMA2 packed; broadcast
// LDS.128 W reads; red.global.add.v4 scatter into pre-initialized target.
// ---------------------------------------------------------------------------
template <int K>
__global__ void pairconv16_kernel(size_t pbase, int cbase,
                                  const float* __restrict__ y,
                                  const float* __restrict__ Wg,  // [K,16,16]
                                  float* __restrict__ out) {
    __shared__ float4 Ws[K * 64];
    __shared__ int sP;
    if (threadIdx.x == 0) sP = g_kbase[cbase + K];
    __syncthreads();
    int P = sP;
    if (blockIdx.x * blockDim.x >= P) return;
    for (int t = threadIdx.x; t < K * 64; t += blockDim.x)
        Ws[t] = __ldg((const float4*)Wg + t);
    __syncthreads();

    for (int t = blockIdx.x * blockDim.x + threadIdx.x; t < P;
         t += gridDim.x * blockDim.x) {
        int2 pr = __ldg(&g_pairs[pbase + t]);
        int k = pr.x >> 20;
        int oi = pr.x & 0xFFFFF;
        const float4* yr = (const float4*)(y + (size_t)pr.y * 16);
        float4 y0 = __ldg(yr + 0), y1 = __ldg(yr + 1);
        float4 y2 = __ldg(yr + 2), y3 = __ldg(yr + 3);
        const ulonglong2* Wk = (const ulonglong2*)(Ws + (size_t)k * 64);
        unsigned long long a0 = 0, a1 = 0, a2 = 0, a3 = 0,
                           a4 = 0, a5 = 0, a6 = 0, a7 = 0;
        JSTEP16(Wk, y0, y1, y2, y3, a0, a1, a2, a3, a4, a5, a6, a7)

        float* op = out + (size_t)oi * 16;
        float2 f0 = up2(a0), f1 = up2(a1), f2 = up2(a2), f3 = up2(a3);
        float2 f4 = up2(a4), f5 = up2(a5), f6 = up2(a6), f7 = up2(a7);
        red4(op + 0,  make_float4(f0.x, f0.y, f1.x, f1.y));
        red4(op + 4,  make_float4(f2.x, f2.y, f3.x, f3.y));
        red4(op + 8,  make_float4(f4.x, f4.y, f5.x, f5.y));
        red4(op + 12, make_float4(f6.x, f6.y, f7.x, f7.y));
    }
}

// p1 pair conv: Cin=2 -> 16, non-self rb0 pairs, raw feats
__global__ void pairconv_p1_kernel(const float* __restrict__ feats,
                                   const float* __restrict__ Wg,  // [27,2,16]
                                   float* __restrict__ out) {
    __shared__ float4 Ws[27 * 8];
    __shared__ int sP;
    if (threadIdx.x == 0) sP = g_kbase[27];
    __syncthreads();
    int P = sP;
    if (blockIdx.x * blockDim.x >= P) return;
    for (int t = threadIdx.x; t < 27 * 8; t += blockDim.x)
        Ws[t] = __ldg((const float4*)Wg + t);
    __syncthreads();

    for (int t = blockIdx.x * blockDim.x + threadIdx.x; t < P;
         t += gridDim.x * blockDim.x) {
        int2 pr = __ldg(&g_pairs[RB0_P + t]);
        int k = pr.x >> 20;
        int oi = pr.x & 0xFFFFF;
        float2 f = __ldg((const float2*)(feats + (size_t)pr.y * 2));
        const float4* Wk = &Ws[k * 8];
        float4 u0 = Wk[0], u1 = Wk[1], u2 = Wk[2], u3 = Wk[3];
        float4 v0 = Wk[4], v1 = Wk[5], v2 = Wk[6], v3 = Wk[7];
        float4 a0 = make_float4(fmaf(f.y, v0.x, f.x * u0.x), fmaf(f.y, v0.y, f.x * u0.y),
                                fmaf(f.y, v0.z, f.x * u0.z), fmaf(f.y, v0.w, f.x * u0.w));
        float4 a1 = make_float4(fmaf(f.y, v1.x, f.x * u1.x), fmaf(f.y, v1.y, f.x * u1.y),
                                fmaf(f.y, v1.z, f.x * u1.z), fmaf(f.y, v1.w, f.x * u1.w));
        float4 a2 = make_float4(fmaf(f.y, v2.x, f.x * u2.x), fmaf(f.y, v2.y, f.x * u2.y),
                                fmaf(f.y, v2.z, f.x * u2.z), fmaf(f.y, v2.w, f.x * u2.w));
        float4 a3 = make_float4(fmaf(f.y, v3.x, f.x * u3.x), fmaf(f.y, v3.y, f.x * u3.y),
                                fmaf(f.y, v3.z, f.x * u3.z), fmaf(f.y, v3.w, f.x * u3.w));
        float* op = out + (size_t)oi * 16;
        red4(op + 0, a0); red4(op + 4, a1); red4(op + 8, a2); red4(op + 12, a3);
    }
}

// p1 self init: X0[i] = feats[i] . W_p1[13]  (dense, replaces memset)
__global__ void init_p1_kernel(const float* __restrict__ feats,
                               const float* __restrict__ Wg,  // [27,2,16]
                               float* __restrict__ out, int N) {
    __shared__ float4 Ws[8];
    if (threadIdx.x < 8) Ws[threadIdx.x] = __ldg((const float4*)Wg + 13 * 8 + threadIdx.x);
    __syncthreads();
    int i = blockIdx.x * blockDim.x + threadIdx.x;
    if (i >= N) return;
    float2 f = __ldg((const float2*)(feats + (size_t)i * 2));
    float4* o = (float4*)(out + (size_t)i * 16);
#pragma unroll
    for (int q = 0; q < 4; q++) {
        float4 u = Ws[q], v = Ws[4 + q];
        o[q] = make_float4(fmaf(f.y, v.x, f.x * u.x), fmaf(f.y, v.y, f.x * u.y),
                           fmaf(f.y, v.z, f.x * u.z), fmaf(f.y, v.w, f.x * u.w));
    }
}

// ---------------------------------------------------------------------------
// FUSED: stats(X) -> [grid barrier + BN finalize] -> y=relu(X*sc+sh), and
// target = Wself^T y (+ target if addTo). Lean (<=64 regs), co-resident grid.
// ---------------------------------------------------------------------------
__global__ void __launch_bounds__(256, 4)
rbself_kernel(const float* __restrict__ X, int N,
              const float* __restrict__ gg, const float* __restrict__ bb,
              float invN,
              const float* __restrict__ Wself,   // [16,16]
              float* __restrict__ y,
              float* __restrict__ target, int addTo) {
    __shared__ float4 Ws[64];
    __shared__ float ws[8][32];
    unsigned base = *(volatile unsigned*)&g_epoch;
    if (threadIdx.x < 64) Ws[threadIdx.x] = __ldg((const float4*)Wself + threadIdx.x);

    // phase A: stats
    {
        float s[16], q[16];
#pragma unroll
        for (int c = 0; c < 16; c++) { s[c] = 0.f; q[c] = 0.f; }
        for (int i = blockIdx.x * 256 + threadIdx.x; i < N; i += gridDim.x * 256) {
            const float4* xr = (const float4*)(X + (size_t)i * 16);
#pragma unroll
            for (int t = 0; t < 4; t++) {
                float4 v = __ldg(xr + t);
                s[4*t+0] += v.x; q[4*t+0] += v.x*v.x;
                s[4*t+1] += v.y; q[4*t+1] += v.y*v.y;
                s[4*t+2] += v.z; q[4*t+2] += v.z*v.z;
                s[4*t+3] += v.w; q[4*t+3] += v.w*v.w;
            }
        }
        stats_flush(s, q, 0, ws);
    }
    grid_sync_fin(base + 1, gg, bb, invN, 16);

    // phase B: bnrelu + self GEMM
    float sc[16], sh[16];
#pragma unroll
    for (int c = 0; c < 16; c++) { sc[c] = __ldcg(&g_scale[c]); sh[c] = __ldcg(&g_shift[c]); }
    for (int i = blockIdx.x * 256 + threadIdx.x; i < N; i += gridDim.x * 256) {
        const float4* xr = (const float4*)(X + (size_t)i * 16);
        float4* yr = (float4*)(y + (size_t)i * 16);
        float v[16];
#pragma unroll
        for (int q = 0; q < 4; q++) {
            float4 t = __ldg(xr + q);
            t.x = fmaxf(fmaf(t.x, sc[4*q+0], sh[4*q+0]), 0.f);
            t.y = fmaxf(fmaf(t.y, sc[4*q+1], sh[4*q+1]), 0.f);
            t.z = fmaxf(fmaf(t.z, sc[4*q+2], sh[4*q+2]), 0.f);
            t.w = fmaxf(fmaf(t.w, sc[4*q+3], sh[4*q+3]), 0.f);
            yr[q] = t;
            v[4*q+0] = t.x; v[4*q+1] = t.y; v[4*q+2] = t.z; v[4*q+3] = t.w;
        }
        float4 a0 = make_float4(0.f,0.f,0.f,0.f), a1 = a0, a2 = a0, a3 = a0;
#pragma unroll
        for (int j = 0; j < 16; j++) {
            float yv = v[j];
            float4 w0 = Ws[4*j+0], w1 = Ws[4*j+1], w2 = Ws[4*j+2], w3 = Ws[4*j+3];
            a0.x = fmaf(yv,w0.x,a0.x); a0.y = fmaf(yv,w0.y,a0.y);
            a0.z = fmaf(yv,w0.z,a0.z); a0.w = fmaf(yv,w0.w,a0.w);
            a1.x = fmaf(yv,w1.x,a1.x); a1.y = fmaf(yv,w1.y,a1.y);
            a1.z = fmaf(yv,w1.z,a1.z); a1.w = fmaf(yv,w1.w,a1.w);
            a2.x = fmaf(yv,w2.x,a2.x); a2.y = fmaf(yv,w2.y,a2.y);
            a2.z = fmaf(yv,w2.z,a2.z); a2.w = fmaf(yv,w2.w,a2.w);
            a3.x = fmaf(yv,w3.x,a3.x); a3.y = fmaf(yv,w3.y,a3.y);
            a3.z = fmaf(yv,w3.z,a3.z); a3.w = fmaf(yv,w3.w,a3.w);
        }
        float4* tg = (float4*)(target + (size_t)i * 16);
        if (addTo) {
            float4 r0 = tg[0], r1 = tg[1], r2 = tg[2], r3 = tg[3];
            a0.x += r0.x; a0.y += r0.y; a0.z += r0.z; a0.w += r0.w;
            a1.x += r1.x; a1.y += r1.y; a1.z += r1.z; a1.w += r1.w;
            a2.x += r2.x; a2.y += r2.y; a2.z += r2.z; a2.w += r2.w;
            a3.x += r3.x; a3.y += r3.y; a3.z += r3.z; a3.w += r3.w;
        }
        tg[0] = a0; tg[1] = a1; tg[2] = a2; tg[3] = a3;
    }
}

// ---------------------------------------------------------------------------
// FUSED: stats(X) -> [barrier + finalize] -> y=relu(...) and zero target[Nz].
// ---------------------------------------------------------------------------
__global__ void __launch_bounds__(256, 4)
rbzero_kernel(const float* __restrict__ X, int N,
              const float* __restrict__ gg, const float* __restrict__ bb,
              float invN,
              float* __restrict__ y,
              float* __restrict__ zb, int Nz) {
    __shared__ float ws[8][32];
    unsigned base = *(volatile unsigned*)&g_epoch;
    {
        float s[16], q[16];
#pragma unroll
        for (int c = 0; c < 16; c++) { s[c] = 0.f; q[c] = 0.f; }
        for (int i = blockIdx.x * 256 + threadIdx.x; i < N; i += gridDim.x * 256) {
            const float4* xr = (const float4*)(X + (size_t)i * 16);
#pragma unroll
            for (int t = 0; t < 4; t++) {
                float4 v = __ldg(xr + t);
                s[4*t+0] += v.x; q[4*t+0] += v.x*v.x;
                s[4*t+1] += v.y; q[4*t+1] += v.y*v.y;
                s[4*t+2] += v.z; q[4*t+2] += v.z*v.z;
                s[4*t+3] += v.w; q[4*t+3] += v.w*v.w;
            }
        }
        stats_flush(s, q, 0, ws);
    }
    grid_sync_fin(base + 1, gg, bb, invN, 16);

    float sc[16], sh[16];
#pragma unroll
    for (int c = 0; c < 16; c++) { sc[c] = __ldcg(&g_scale[c]); sh[c] = __ldcg(&g_shift[c]); }
    int M = (N > Nz) ? N : Nz;
    for (int i = blockIdx.x * 256 + threadIdx.x; i < M; i += gridDim.x * 256) {
        if (i < N) {
            const float4* xr = (const float4*)(X + (size_t)i * 16);
            float4* yr = (float4*)(y + (size_t)i * 16);
#pragma unroll
            for (int q = 0; q < 4; q++) {
                float4 t = __ldg(xr + q);
                t.x = fmaxf(fmaf(t.x, sc[4*q+0], sh[4*q+0]), 0.f);
                t.y = fmaxf(fmaf(t.y, sc[4*q+1], sh[4*q+1]), 0.f);
                t.z = fmaxf(fmaf(t.z, sc[4*q+2], sh[4*q+2]), 0.f);
                t.w = fmaxf(fmaf(t.w, sc[4*q+3], sh[4*q+3]), 0.f);
                yr[q] = t;
            }
        }
        if (i < Nz) {
            float4* zr = (float4*)(zb + (size_t)i * 16);
            float4 z = make_float4(0.f, 0.f, 0.f, 0.f);
            zr[0] = z; zr[1] = z; zr[2] = z; zr[3] = z;
        }
    }
}

// ---------------------------------------------------------------------------
// FUSED join: gathered 48-ch stats -> [barrier + finalize48] -> BN3-ReLU+SDF.
// ---------------------------------------------------------------------------
__global__ void __launch_bounds__(256, 4)
joinfinal_kernel(const float* __restrict__ x0, const float* __restrict__ x1,
                 const float* __restrict__ x2,
                 const int* __restrict__ p01, const int* __restrict__ p12,
                 int N0,
                 const float* __restrict__ bn3g, const float* __restrict__ bn3b,
                 const float* __restrict__ wsdf, const float* __restrict__ bsdf,
                 float* __restrict__ out) {
    __shared__ float ws[8][32];
    __shared__ float sw[48], ssc[48], ssh[48];
    unsigned base = *(volatile unsigned*)&g_epoch;

#pragma unroll 1
    for (int srcId = 0; srcId < 3; srcId++) {
        const float* x = (srcId == 0) ? x0 : (srcId == 1) ? x1 : x2;
        float s[16], q[16];
#pragma unroll
        for (int c = 0; c < 16; c++) { s[c] = 0.f; q[c] = 0.f; }
        for (int i = blockIdx.x * 256 + threadIdx.x; i < N0; i += gridDim.x * 256) {
            int r = i;
            if (srcId >= 1) r = __ldg(p01 + i);
            if (srcId == 2) r = __ldg(p12 + r);
            const float4* xr = (const float4*)(x + (size_t)r * 16);
#pragma unroll
            for (int t = 0; t < 4; t++) {
                float4 v = __ldg(xr + t);
                s[4*t+0] += v.x; q[4*t+0] += v.x*v.x;
                s[4*t+1] += v.y; q[4*t+1] += v.y*v.y;
                s[4*t+2] += v.z; q[4*t+2] += v.z*v.z;
                s[4*t+3] += v.w; q[4*t+3] += v.w*v.w;
            }
        }
        stats_flush(s, q, srcId * 16, ws);
    }
    grid_sync_fin(base + 1, bn3g, bn3b, 1.0f / N0, 48);

    if (threadIdx.x < 48) {
        sw[threadIdx.x] = __ldg(wsdf + threadIdx.x);
        ssc[threadIdx.x] = __ldcg(&g_scale[threadIdx.x]);
        ssh[threadIdx.x] = __ldcg(&g_shift[threadIdx.x]);
    }
    __syncthreads();

    float bs = __ldg(bsdf);
    for (int i = blockIdx.x * 256 + threadIdx.x; i < N0; i += gridDim.x * 256) {
        int p = __ldg(p01 + i);
        int qq = __ldg(p12 + p);
        float r = bs;
        const float* rows[3] = { x0 + (size_t)i * 16, x1 + (size_t)p * 16,
                                 x2 + (size_t)qq * 16 };
#pragma unroll
        for (int gidx = 0; gidx < 3; gidx++) {
            const float4* xr = (const float4*)rows[gidx];
#pragma unroll
            for (int t = 0; t < 4; t++) {
                float4 v = __ldg(xr + t);
                int c = gidx * 16 + t * 4;
                r += fmaxf(fmaf(v.x, ssc[c+0], ssh[c+0]), 0.f) * sw[c+0];
                r += fmaxf(fmaf(v.y, ssc[c+1], ssh[c+1]), 0.f) * sw[c+1];
                r += fmaxf(fmaf(v.z, ssc[c+2], ssh[c+2]), 0.f) * sw[c+2];
                r += fmaxf(fmaf(v.w, ssc[c+3], ssh[c+3]), 0.f) * sw[c+3];
            }
        }
        out[i] = r;
    }
}

// ---------------------------------------------------------------------------
// Host orchestration
// ---------------------------------------------------------------------------
static inline int gdiv(int n, int t) { return (n + t - 1) / t; }
static inline int capg(int g) { return g < 592 ? g : 592; }  // 4 blk/SM co-resident

extern "C" void kernel_launch(void* const* d_in, const int* in_sizes, int n_in,
                              void* d_out, int out_size) {
    const float* feats = (const float*)d_in[0];
    const float* w_p1  = (const float*)d_in[1];
    const float* bn1g  = (const float*)d_in[2];
    const float* bn1b  = (const float*)d_in[3];
    const float* w1    = (const float*)d_in[4];
    const float* bn2g  = (const float*)d_in[5];
    const float* bn2b  = (const float*)d_in[6];
    const float* w2    = (const float*)d_in[7];
    const float* dbng  = (const float*)d_in[8];
    const float* dbnb  = (const float*)d_in[9];
    const float* dw    = (const float*)d_in[10];
    const float* bn3g  = (const float*)d_in[11];
    const float* bn3b  = (const float*)d_in[12];
    const float* wsdf  = (const float*)d_in[13];
    const float* bsdf  = (const float*)d_in[14];
    const int* nbr0    = (const int*)d_in[15];
    const int* nbr1    = (const int*)d_in[16];
    const int* nbr2    = (const int*)d_in[17];
    const int* down01  = (const int*)d_in[18];
    const int* down12  = (const int*)d_in[19];
    const int* p01     = (const int*)d_in[20];
    const int* p12     = (const int*)d_in[21];

    int N0 = in_sizes[0] / 2;
    int N1 = in_sizes[16] / 27;
    int N2 = in_sizes[17] / 27;

    float *X0, *X1, *X2, *T1, *T2;
    cudaGetSymbolAddress((void**)&X0, g_X0);
    cudaGetSymbolAddress((void**)&X1, g_X1);
    cudaGetSymbolAddress((void**)&X2, g_X2);
    cudaGetSymbolAddress((void**)&T1, g_T1);
    cudaGetSymbolAddress((void**)&T2, g_T2);

    const int T = 256;
    const int PG = 1184;
    int B0 = gdiv(N0, T), B1 = gdiv(N1, T), B2 = gdiv(N2, T);
    int F0 = capg(B0), F1 = capg(B1), F2 = capg(B2);

    int Bc0 = B0, Bc01 = B0 + B1, Bc012 = Bc01 + B2, Bc0123 = Bc012 + B1;
    int Ball = Bc0123 + B2;

    // ---- compaction (self offsets excluded; preloaded loads for MLP) ----
    zero_misc_kernel<<<1, 128>>>();
    count_all_kernel<<<Ball, T>>>(nbr0, nbr1, nbr2, down01, down12,
                                  N0, N1, N2, Bc0, Bc01, Bc012, Bc0123);
    scan_rows_kernel<<<97, 256>>>(gdiv(N0, 32), gdiv(N1, 32), gdiv(N2, 32),
                                  gdiv(N1, 32), gdiv(N2, 32));
    bucket_base_kernel<<<1, 160>>>();
    fill_all_kernel<<<Ball, T>>>(nbr0, nbr1, nbr2, down01, down12,
                                 N0, N1, N2, Bc0, Bc01, Bc012, Bc0123);

    // ---- level 0 ----
    init_p1_kernel<<<B0, T>>>(feats, w_p1, X0, N0);
    pairconv_p1_kernel<<<PG, T>>>(feats, w_p1, X0);                     // X0 = x

    rbself_kernel<<<F0, T>>>(X0, N0, bn1g + 0, bn1b + 0, 1.0f / N0,
                             w1 + 0 * 6912 + 13 * 256, T1, T2, 0);
    pairconv16_kernel<27><<<PG, T>>>(RB0_P, 0, T1, w1 + 0 * 6912, T2);  // T2 = h1

    rbself_kernel<<<F0, T>>>(T2, N0, bn2g + 0, bn2b + 0, 1.0f / N0,
                             w2 + 0 * 6912 + 13 * 256, T1, X0, 1);
    pairconv16_kernel<27><<<PG, T>>>(RB0_P, 0, T1, w2 + 0 * 6912, X0);  // X0 = r0

    rbzero_kernel<<<F0, T>>>(X0, N0, dbng + 0, dbnb + 0, 1.0f / N0, T1, X1, N1);
    pairconv16_kernel<8><<<PG, T>>>(RB3_P, 96, T1, dw + 0 * 2048, X1);  // X1 = y1

    // ---- level 1 ----
    rbself_kernel<<<F1, T>>>(X1, N1, bn1g + 16, bn1b + 16, 1.0f / N1,
                             w1 + 1 * 6912 + 13 * 256, T1, T2, 0);
    pairconv16_kernel<27><<<PG, T>>>(RB1_P, 32, T1, w1 + 1 * 6912, T2);

    rbself_kernel<<<F1, T>>>(T2, N1, bn2g + 16, bn2b + 16, 1.0f / N1,
                             w2 + 1 * 6912 + 13 * 256, T1, X1, 1);
    pairconv16_kernel<27><<<PG, T>>>(RB1_P, 32, T1, w2 + 1 * 6912, X1); // X1 = r1

    rbzero_kernel<<<F1, T>>>(X1, N1, dbng + 16, dbnb + 16, 1.0f / N1, T1, X2, N2);
    pairconv16_kernel<8><<<PG, T>>>(RB4_P, 128, T1, dw + 1 * 2048, X2); // X2 = z2

    // ---- level 2 ----
    rbself_kernel<<<F2, T>>>(X2, N2, bn1g + 32, bn1b + 32, 1.0f / N2,
                             w1 + 2 * 6912 + 13 * 256, T1, T2, 0);
    pairconv16_kernel<27><<<PG, T>>>(RB2_P, 64, T1, w1 + 2 * 6912, T2);

    rbself_kernel<<<F2, T>>>(T2, N2, bn2g + 32, bn2b + 32, 1.0f / N2,
                             w2 + 2 * 6912 + 13 * 256, T1, X2, 1);
    pairconv16_kernel<27><<<PG, T>>>(RB2_P, 64, T1, w2 + 2 * 6912, X2); // X2 = r2

    // ---- join + BN3 + SDF head (fused) ----
    joinfinal_kernel<<<F0, T>>>(X0, X1, X2, p01, p12, N0,
                                bn3g, bn3b, wsdf, bsdf, (float*)d_out);
}

// round 12
// speedup vs baseline: 1.1786x; 1.1786x over previous
#include <cuda_runtime.h>

#define N0MAX 500000
#define WMAX  15680          // >= gdiv(N0MAX, 32)
#define EPS   1e-4f

// ---------------------------------------------------------------------------
// Scratch (device globals — no runtime allocation allowed)
// ---------------------------------------------------------------------------
__device__ float g_X0[N0MAX * 16];
__device__ float g_X1[N0MAX * 16];
__device__ float g_X2[N0MAX * 16];
__device__ float g_T1[N0MAX * 16];
__device__ float g_T2[N0MAX * 16];
// flat pair lists per rulebook; pair = ((k<<20)|out_i, in_idx)
__device__ int2     g_pairs[(size_t)97 * N0MAX];
__device__ int      g_wcnt[160 * WMAX];   // per-(rb k, warp) counts -> bases
__device__ int      g_cnt[160];           // per-(rb k) totals
__device__ int      g_kbase[160];         // per-(rb k) flat base; [cbase+K]=total
__device__ float    g_stats[96];          // sum[0..47], sumsq[48..95]
__device__ float    g_scale[48];
__device__ float    g_shift[48];
__device__ unsigned g_ticket;

#define RB0_P ((size_t)0)
#define RB1_P ((size_t)27 * N0MAX)
#define RB2_P ((size_t)54 * N0MAX)
#define RB3_P ((size_t)81 * N0MAX)
#define RB4_P ((size_t)89 * N0MAX)

// ---------------------------------------------------------------------------
// f32x2 packed-math helpers (sm_103a FFMA2 — only reachable via PTX)
// ---------------------------------------------------------------------------
__device__ __forceinline__ unsigned long long fma2(unsigned long long a,
                                                   unsigned long long b,
                                                   unsigned long long c) {
    unsigned long long d;
    asm("fma.rn.f32x2 %0, %1, %2, %3;" : "=l"(d) : "l"(a), "l"(b), "l"(c));
    return d;
}
__device__ __forceinline__ unsigned long long dup2(float v) {
    unsigned long long d;
    asm("mov.b64 %0, {%1, %1};" : "=l"(d) : "f"(v));
    return d;
}
__device__ __forceinline__ float2 up2(unsigned long long v) {
    float2 f;
    asm("mov.b64 {%0, %1}, %2;" : "=f"(f.x), "=f"(f.y) : "l"(v));
    return f;
}
__device__ __forceinline__ void red4(float* p, float4 v) {
    asm volatile("red.global.add.v4.f32 [%0], {%1, %2, %3, %4};"
                 :: "l"(p), "f"(v.x), "f"(v.y), "f"(v.z), "f"(v.w) : "memory");
}

#define JSTEP2(Wk, jj, yv, a0, a1, a2, a3, a4, a5, a6, a7) { \
    unsigned long long yy = dup2(yv); \
    ulonglong2 p0 = (Wk)[4*(jj)+0], p1 = (Wk)[4*(jj)+1]; \
    ulonglong2 p2 = (Wk)[4*(jj)+2], p3 = (Wk)[4*(jj)+3]; \
    a0 = fma2(yy, p0.x, a0); a1 = fma2(yy, p0.y, a1); \
    a2 = fma2(yy, p1.x, a2); a3 = fma2(yy, p1.y, a3); \
    a4 = fma2(yy, p2.x, a4); a5 = fma2(yy, p2.y, a5); \
    a6 = fma2(yy, p3.x, a6); a7 = fma2(yy, p3.y, a7); }

#define JSTEP16(Wk, y0, y1, y2, y3, a0, a1, a2, a3, a4, a5, a6, a7) \
    JSTEP2(Wk, 0,  y0.x, a0,a1,a2,a3,a4,a5,a6,a7) \
    JSTEP2(Wk, 1,  y0.y, a0,a1,a2,a3,a4,a5,a6,a7) \
    JSTEP2(Wk, 2,  y0.z, a0,a1,a2,a3,a4,a5,a6,a7) \
    JSTEP2(Wk, 3,  y0.w, a0,a1,a2,a3,a4,a5,a6,a7) \
    JSTEP2(Wk, 4,  y1.x, a0,a1,a2,a3,a4,a5,a6,a7) \
    JSTEP2(Wk, 5,  y1.y, a0,a1,a2,a3,a4,a5,a6,a7) \
    JSTEP2(Wk, 6,  y1.z, a0,a1,a2,a3,a4,a5,a6,a7) \
    JSTEP2(Wk, 7,  y1.w, a0,a1,a2,a3,a4,a5,a6,a7) \
    JSTEP2(Wk, 8,  y2.x, a0,a1,a2,a3,a4,a5,a6,a7) \
    JSTEP2(Wk, 9,  y2.y, a0,a1,a2,a3,a4,a5,a6,a7) \
    JSTEP2(Wk, 10, y2.z, a0,a1,a2,a3,a4,a5,a6,a7) \
    JSTEP2(Wk, 11, y2.w, a0,a1,a2,a3,a4,a5,a6,a7) \
    JSTEP2(Wk, 12, y3.x, a0,a1,a2,a3,a4,a5,a6,a7) \
    JSTEP2(Wk, 13, y3.y, a0,a1,a2,a3,a4,a5,a6,a7) \
    JSTEP2(Wk, 14, y3.z, a0,a1,a2,a3,a4,a5,a6,a7) \
    JSTEP2(Wk, 15, y3.w, a0,a1,a2,a3,a4,a5,a6,a7)

// ---------------------------------------------------------------------------
__global__ void zero_misc_kernel() {
    int t = threadIdx.x;
    if (t < 96) g_stats[t] = 0.0f;
    if (t == 0) g_ticket = 0u;
}

// ---------------------------------------------------------------------------
// Compaction phase 1: per-(k, warp) active counts. PRELOADED nbr reads
// (registers, MLP~K) — the previous #pragma unroll 1 form was MLP=1,
// latency-bound @30us/pass (17% DRAM). k==13 excluded for K=27 rulebooks.
// ---------------------------------------------------------------------------
template <int K>
__device__ __forceinline__ void count_dev(const int* __restrict__ nbr,
                                          int Nout, int Nin, int cbase, int lb) {
    int i = lb * 256 + threadIdx.x;
    bool inb = i < Nout;
    int lane = threadIdx.x & 31;
    int w = i >> 5;
    int idx[K];
#pragma unroll
    for (int k = 0; k < K; k++)
        idx[k] = inb ? __ldg(nbr + (size_t)k * Nout + i) : Nin;
#pragma unroll
    for (int k = 0; k < K; k++) {
        if (K == 27 && k == 13) continue;
        unsigned m = __ballot_sync(0xffffffffu, idx[k] < Nin);
        if (lane == 0) g_wcnt[(size_t)(cbase + k) * WMAX + w] = __popc(m);
    }
}

__global__ void count_all_kernel(const int* nbr0, const int* nbr1,
                                 const int* nbr2, const int* d01,
                                 const int* d12, int N0, int N1, int N2,
                                 int B0, int B01, int B012, int B0123) {
    int b = blockIdx.x;
    if (b < B0)           count_dev<27>(nbr0, N0, N0, 0,   b);
    else if (b < B01)     count_dev<27>(nbr1, N1, N1, 32,  b - B0);
    else if (b < B012)    count_dev<27>(nbr2, N2, N2, 64,  b - B01);
    else if (b < B0123)   count_dev<8> (d01,  N1, N0, 96,  b - B012);
    else                  count_dev<8> (d12,  N2, N1, 128, b - B0123);
}

// ---------------------------------------------------------------------------
// Compaction phase 2: exclusive scan per (rb, k) row; one block per row.
// Rows 13/45/77 (self buckets) get zero totals.
// ---------------------------------------------------------------------------
__global__ void scan_rows_kernel(int nw0, int nw1, int nw2, int nw3, int nw4) {
    int b = blockIdx.x;
    int row, nw;
    if (b < 27)      { row = b;            nw = nw0; }
    else if (b < 54) { row = 32 + b - 27;  nw = nw1; }
    else if (b < 81) { row = 64 + b - 54;  nw = nw2; }
    else if (b < 89) { row = 96 + b - 81;  nw = nw3; }
    else             { row = 128 + b - 89; nw = nw4; }
    if (row == 13 || row == 45 || row == 77) {
        if (threadIdx.x == 0) g_cnt[row] = 0;
        return;
    }
    int* p = g_wcnt + (size_t)row * WMAX;
    int t = threadIdx.x, lane = t & 31, wid = t >> 5;
    __shared__ int wtot[8];
    __shared__ int carry;
    if (t == 0) carry = 0;
    __syncthreads();
    for (int base = 0; base < nw; base += 256) {
        int v = (base + t < nw) ? p[base + t] : 0;
        int x = v;
#pragma unroll
        for (int off = 1; off < 32; off <<= 1) {
            int yv = __shfl_up_sync(0xffffffffu, x, off);
            if (lane >= off) x += yv;
        }
        if (lane == 31) wtot[wid] = x;
        __syncthreads();
        int wofs = 0;
#pragma unroll
        for (int w2 = 0; w2 < 8; w2++) wofs += (w2 < wid) ? wtot[w2] : 0;
        if (base + t < nw) p[base + t] = x - v + wofs + carry;
        __syncthreads();
        if (t == 0) {
            int s = 0;
#pragma unroll
            for (int w2 = 0; w2 < 8; w2++) s += wtot[w2];
            carry += s;
        }
        __syncthreads();
    }
    if (t == 0) g_cnt[row] = carry;
}

// Per-rb exclusive scan over k -> flat bucket bases + totals (1 warp per rb).
__global__ void bucket_base_kernel() {
    int wid = threadIdx.x >> 5;
    int lane = threadIdx.x & 31;
    if (wid >= 5) return;
    const int cb[5] = {0, 32, 64, 96, 128};
    const int kk[5] = {27, 27, 27, 8, 8};
    int K = kk[wid], base = cb[wid];
    int v = (lane < K) ? __ldg(&g_cnt[base + lane]) : 0;
    int x = v;
#pragma unroll
    for (int off = 1; off < 32; off <<= 1) {
        int yv = __shfl_up_sync(0xffffffffu, x, off);
        if (lane >= off) x += yv;
    }
    if (lane < K) g_kbase[base + lane] = x - v;
    int tot = __shfl_sync(0xffffffffu, x, K - 1);
    if (lane == K) g_kbase[base + K] = tot;
}

// ---------------------------------------------------------------------------
// Compaction phase 3: PRELOADED fill; write pairs at flat slots; skip k==13.
// ---------------------------------------------------------------------------
template <int K>
__device__ __forceinline__ void fill_dev(const int* __restrict__ nbr,
                                         int Nout, int Nin, int cbase,
                                         size_t pbase, int lb) {
    int i = lb * 256 + threadIdx.x;
    bool inb = i < Nout;
    int lane = threadIdx.x & 31;
    int w = i >> 5;
    unsigned lt = (1u << lane) - 1u;
    int idx[K];
#pragma unroll
    for (int k = 0; k < K; k++)
        idx[k] = inb ? __ldg(nbr + (size_t)k * Nout + i) : Nin;
#pragma unroll
    for (int k = 0; k < K; k++) {
        if (K == 27 && k == 13) continue;
        bool act = idx[k] < Nin;
        unsigned m = __ballot_sync(0xffffffffu, act);
        if (!m) continue;
        int base = __ldg(&g_kbase[cbase + k]) +
                   __ldg(&g_wcnt[(size_t)(cbase + k) * WMAX + w]);
        if (act)
            g_pairs[pbase + base + __popc(m & lt)] =
                make_int2((k << 20) | i, idx[k]);
    }
}

__global__ void fill_all_kernel(const int* nbr0, const int* nbr1,
                                const int* nbr2, const int* d01,
                                const int* d12, int N0, int N1, int N2,
                                int B0, int B01, int B012, int B0123) {
    int b = blockIdx.x;
    if (b < B0)           fill_dev<27>(nbr0, N0, N0, 0,   RB0_P, b);
    else if (b < B01)     fill_dev<27>(nbr1, N1, N1, 32,  RB1_P, b - B0);
    else if (b < B012)    fill_dev<27>(nbr2, N2, N2, 64,  RB2_P, b - B01);
    else if (b < B0123)   fill_dev<8> (d01,  N1, N0, 96,  RB3_P, b - B012);
    else                  fill_dev<8> (d12,  N2, N1, 128, RB4_P, b - B0123);
}

// ---------------------------------------------------------------------------
// Pair-parallel sparse conv 16->16 (non-self offsets only), FFMA2 packed.
// k warp-uniform within a bucket -> broadcast LDS.128 W reads.
// red.global.add.v4 scatter into pre-initialized target.
// ---------------------------------------------------------------------------
template <int K>
__global__ void pairconv16_kernel(size_t pbase, int cbase,
                                  const float* __restrict__ y,
                                  const float* __restrict__ Wg,  // [K,16,16]
                                  float* __restrict__ out) {
    __shared__ float4 Ws[K * 64];
    __shared__ int sP;
    if (threadIdx.x == 0) sP = g_kbase[cbase + K];
    __syncthreads();
    int P = sP;
    if (blockIdx.x * blockDim.x >= P) return;
    for (int t = threadIdx.x; t < K * 64; t += blockDim.x)
        Ws[t] = __ldg((const float4*)Wg + t);
    __syncthreads();

    for (int t = blockIdx.x * blockDim.x + threadIdx.x; t < P;
         t += gridDim.x * blockDim.x) {
        int2 pr = __ldg(&g_pairs[pbase + t]);
        int k = pr.x >> 20;
        int oi = pr.x & 0xFFFFF;
        const float4* yr = (const float4*)(y + (size_t)pr.y * 16);
        float4 y0 = __ldg(yr + 0), y1 = __ldg(yr + 1);
        float4 y2 = __ldg(yr + 2), y3 = __ldg(yr + 3);
        const ulonglong2* Wk = (const ulonglong2*)(Ws + (size_t)k * 64);
        unsigned long long a0 = 0, a1 = 0, a2 = 0, a3 = 0,
                           a4 = 0, a5 = 0, a6 = 0, a7 = 0;
        JSTEP16(Wk, y0, y1, y2, y3, a0, a1, a2, a3, a4, a5, a6, a7)

        float* op = out + (size_t)oi * 16;
        float2 f0 = up2(a0), f1 = up2(a1), f2 = up2(a2), f3 = up2(a3);
        float2 f4 = up2(a4), f5 = up2(a5), f6 = up2(a6), f7 = up2(a7);
        red4(op + 0,  make_float4(f0.x, f0.y, f1.x, f1.y));
        red4(op + 4,  make_float4(f2.x, f2.y, f3.x, f3.y));
        red4(op + 8,  make_float4(f4.x, f4.y, f5.x, f5.y));
        red4(op + 12, make_float4(f6.x, f6.y, f7.x, f7.y));
    }
}

// p1 pair conv: Cin=2 -> 16, non-self rb0 pairs, raw feats
__global__ void pairconv_p1_kernel(const float* __restrict__ feats,
                                   const float* __restrict__ Wg,  // [27,2,16]
                                   float* __restrict__ out) {
    __shared__ float4 Ws[27 * 8];
    __shared__ int sP;
    if (threadIdx.x == 0) sP = g_kbase[27];
    __syncthreads();
    int P = sP;
    if (blockIdx.x * blockDim.x >= P) return;
    for (int t = threadIdx.x; t < 27 * 8; t += blockDim.x)
        Ws[t] = __ldg((const float4*)Wg + t);
    __syncthreads();

    for (int t = blockIdx.x * blockDim.x + threadIdx.x; t < P;
         t += gridDim.x * blockDim.x) {
        int2 pr = __ldg(&g_pairs[RB0_P + t]);
        int k = pr.x >> 20;
        int oi = pr.x & 0xFFFFF;
        float2 f = __ldg((const float2*)(feats + (size_t)pr.y * 2));
        const float4* Wk = &Ws[k * 8];
        float4 u0 = Wk[0], u1 = Wk[1], u2 = Wk[2], u3 = Wk[3];
        float4 v0 = Wk[4], v1 = Wk[5], v2 = Wk[6], v3 = Wk[7];
        float4 a0 = make_float4(fmaf(f.y, v0.x, f.x * u0.x), fmaf(f.y, v0.y, f.x * u0.y),
                                fmaf(f.y, v0.z, f.x * u0.z), fmaf(f.y, v0.w, f.x * u0.w));
        float4 a1 = make_float4(fmaf(f.y, v1.x, f.x * u1.x), fmaf(f.y, v1.y, f.x * u1.y),
                                fmaf(f.y, v1.z, f.x * u1.z), fmaf(f.y, v1.w, f.x * u1.w));
        float4 a2 = make_float4(fmaf(f.y, v2.x, f.x * u2.x), fmaf(f.y, v2.y, f.x * u2.y),
                                fmaf(f.y, v2.z, f.x * u2.z), fmaf(f.y, v2.w, f.x * u2.w));
        float4 a3 = make_float4(fmaf(f.y, v3.x, f.x * u3.x), fmaf(f.y, v3.y, f.x * u3.y),
                                fmaf(f.y, v3.z, f.x * u3.z), fmaf(f.y, v3.w, f.x * u3.w));
        float* op = out + (size_t)oi * 16;
        red4(op + 0, a0); red4(op + 4, a1); red4(op + 8, a2); red4(op + 12, a3);
    }
}

// p1 self init: X0[i] = feats[i] . W_p1[13]  (dense, replaces memset)
__global__ void init_p1_kernel(const float* __restrict__ feats,
                               const float* __restrict__ Wg,  // [27,2,16]
                               float* __restrict__ out, int N) {
    __shared__ float4 Ws[8];
    if (threadIdx.x < 8) Ws[threadIdx.x] = __ldg((const float4*)Wg + 13 * 8 + threadIdx.x);
    __syncthreads();
    int i = blockIdx.x * blockDim.x + threadIdx.x;
    if (i >= N) return;
    float2 f = __ldg((const float2*)(feats + (size_t)i * 2));
    float4* o = (float4*)(out + (size_t)i * 16);
#pragma unroll
    for (int q = 0; q < 4; q++) {
        float4 u = Ws[q], v = Ws[4 + q];
        o[q] = make_float4(fmaf(f.y, v.x, f.x * u.x), fmaf(f.y, v.y, f.x * u.y),
                           fmaf(f.y, v.z, f.x * u.z), fmaf(f.y, v.w, f.x * u.w));
    }
}

// ---------------------------------------------------------------------------
// bnrelu + self-contribution init: y = relu(x*scale+shift); target[i] =
// Wself^T y_i (+ target[i] if addTo).
// ---------------------------------------------------------------------------
__global__ void bnrelu_self_kernel(const float* __restrict__ x,
                                   float* __restrict__ y,
                                   const float* __restrict__ Wself, // [16,16]
                                   float* __restrict__ target,
                                   int addTo, int N) {
    __shared__ float4 Ws[64];
    if (threadIdx.x < 64) Ws[threadIdx.x] = __ldg((const float4*)Wself + threadIdx.x);
    __syncthreads();
    int i = blockIdx.x * blockDim.x + threadIdx.x;
    if (i >= N) return;
    const float4* xr = (const float4*)(x + (size_t)i * 16);
    float4* yr = (float4*)(y + (size_t)i * 16);
    float v[16];
#pragma unroll
    for (int q = 0; q < 4; q++) {
        float4 t = __ldg(xr + q);
        t.x = fmaxf(fmaf(t.x, g_scale[4 * q + 0], g_shift[4 * q + 0]), 0.f);
        t.y = fmaxf(fmaf(t.y, g_scale[4 * q + 1], g_shift[4 * q + 1]), 0.f);
        t.z = fmaxf(fmaf(t.z, g_scale[4 * q + 2], g_shift[4 * q + 2]), 0.f);
        t.w = fmaxf(fmaf(t.w, g_scale[4 * q + 3], g_shift[4 * q + 3]), 0.f);
        yr[q] = t;
        v[4 * q + 0] = t.x; v[4 * q + 1] = t.y; v[4 * q + 2] = t.z; v[4 * q + 3] = t.w;
    }
    float4 a0 = make_float4(0.f, 0.f, 0.f, 0.f), a1 = a0, a2 = a0, a3 = a0;
#pragma unroll
    for (int j = 0; j < 16; j++) {
        float yv = v[j];
        float4 w0 = Ws[4 * j + 0], w1 = Ws[4 * j + 1];
        float4 w2 = Ws[4 * j + 2], w3 = Ws[4 * j + 3];
        a0.x = fmaf(yv, w0.x, a0.x); a0.y = fmaf(yv, w0.y, a0.y);
        a0.z = fmaf(yv, w0.z, a0.z); a0.w = fmaf(yv, w0.w, a0.w);
        a1.x = fmaf(yv, w1.x, a1.x); a1.y = fmaf(yv, w1.y, a1.y);
        a1.z = fmaf(yv, w1.z, a1.z); a1.w = fmaf(yv, w1.w, a1.w);
        a2.x = fmaf(yv, w2.x, a2.x); a2.y = fmaf(yv, w2.y, a2.y);
        a2.z = fmaf(yv, w2.z, a2.z); a2.w = fmaf(yv, w2.w, a2.w);
        a3.x = fmaf(yv, w3.x, a3.x); a3.y = fmaf(yv, w3.y, a3.y);
        a3.z = fmaf(yv, w3.z, a3.z); a3.w = fmaf(yv, w3.w, a3.w);
    }
    float4* tg = (float4*)(target + (size_t)i * 16);
    if (addTo) {
        float4 r0 = tg[0], r1 = tg[1], r2 = tg[2], r3 = tg[3];
        a0.x += r0.x; a0.y += r0.y; a0.z += r0.z; a0.w += r0.w;
        a1.x += r1.x; a1.y += r1.y; a1.z += r1.z; a1.w += r1.w;
        a2.x += r2.x; a2.y += r2.y; a2.z += r2.z; a2.w += r2.w;
        a3.x += r3.x; a3.y += r3.y; a3.z += r3.z; a3.w += r3.w;
    }
    tg[0] = a0; tg[1] = a1; tg[2] = a2; tg[3] = a3;
}

// bnrelu + zero-init of a (different-sized) downsample target
__global__ void bnrelu_zero_kernel(const float* __restrict__ x,
                                   float* __restrict__ y,
                                   float* __restrict__ zb, int N, int Nz) {
    int i = blockIdx.x * blockDim.x + threadIdx.x;
    if (i < N) {
        const float4* xr = (const float4*)(x + (size_t)i * 16);
        float4* yr = (float4*)(y + (size_t)i * 16);
#pragma unroll
        for (int q = 0; q < 4; q++) {
            float4 v = __ldg(xr + q);
            v.x = fmaxf(fmaf(v.x, g_scale[4 * q + 0], g_shift[4 * q + 0]), 0.f);
            v.y = fmaxf(fmaf(v.y, g_scale[4 * q + 1], g_shift[4 * q + 1]), 0.f);
            v.z = fmaxf(fmaf(v.z, g_scale[4 * q + 2], g_shift[4 * q + 2]), 0.f);
            v.w = fmaxf(fmaf(v.w, g_scale[4 * q + 3], g_shift[4 * q + 3]), 0.f);
            yr[q] = v;
        }
    }
    if (i < Nz) {
        float4* zr = (float4*)(zb + (size_t)i * 16);
        float4 z = make_float4(0.f, 0.f, 0.f, 0.f);
        zr[0] = z; zr[1] = z; zr[2] = z; zr[3] = z;
    }
}

// ---------------------------------------------------------------------------
// Per-channel sum/sumsq over N rows with BN finalize in last block (Cfin>0).
// ---------------------------------------------------------------------------
__global__ void reduce16_kernel(const float* __restrict__ x, int N,
                                const float* __restrict__ gg,
                                const float* __restrict__ bb,
                                float invN, int Cfin) {
    float s[16], q[16];
#pragma unroll
    for (int c = 0; c < 16; c++) { s[c] = 0.0f; q[c] = 0.0f; }
    for (int i = blockIdx.x * blockDim.x + threadIdx.x; i < N;
         i += gridDim.x * blockDim.x) {
        const float4* xr = (const float4*)(x + (size_t)i * 16);
#pragma unroll
        for (int t = 0; t < 4; t++) {
            float4 v = __ldg(xr + t);
            s[4 * t + 0] += v.x; q[4 * t + 0] += v.x * v.x;
            s[4 * t + 1] += v.y; q[4 * t + 1] += v.y * v.y;
            s[4 * t + 2] += v.z; q[4 * t + 2] += v.z * v.z;
            s[4 * t + 3] += v.w; q[4 * t + 3] += v.w * v.w;
        }
    }
#pragma unroll
    for (int c = 0; c < 16; c++) {
#pragma unroll
        for (int o = 16; o > 0; o >>= 1) {
            s[c] += __shfl_xor_sync(0xffffffffu, s[c], o);
            q[c] += __shfl_xor_sync(0xffffffffu, q[c], o);
        }
    }
    __shared__ float ws[8][32];
    __shared__ bool last;
    int lane = threadIdx.x & 31, wid = threadIdx.x >> 5;
    if (lane == 0) {
#pragma unroll
        for (int c = 0; c < 16; c++) { ws[wid][c] = s[c]; ws[wid][16 + c] = q[c]; }
    }
    __syncthreads();
    if (threadIdx.x < 32) {
        float v = 0.0f;
        int nw = blockDim.x >> 5;
        for (int w = 0; w < nw; w++) v += ws[w][threadIdx.x];
        int t = threadIdx.x;
        atomicAdd(&g_stats[(t < 16) ? t : (48 + t - 16)], v);
    }
    __threadfence();
    if (threadIdx.x == 0) {
        unsigned tk = atomicAdd(&g_ticket, 1u);
        last = (tk == (unsigned)gridDim.x - 1u);
    }
    __syncthreads();
    if (!last) return;
    if (threadIdx.x == 0) g_ticket = 0u;
    int t = threadIdx.x;
    if (t < Cfin) {
        float m = __ldcg(&g_stats[t]) * invN;
        float var = __ldcg(&g_stats[48 + t]) * invN - m * m;
        float sc = __ldg(gg + t) * rsqrtf(var + EPS);
        g_scale[t] = sc;
        g_shift[t] = __ldg(bb + t) - m * sc;
        g_stats[t] = 0.0f;
        g_stats[48 + t] = 0.0f;
    }
}

// ---------------------------------------------------------------------------
// Join stats: 3 sources (x0 direct; x1 via p01; x2 via p01->p12), 48 channels,
// finalize fused into last block.
// ---------------------------------------------------------------------------
__global__ void reduce_join_kernel(const float* __restrict__ x0,
                                   const float* __restrict__ x1,
                                   const float* __restrict__ x2,
                                   const int* __restrict__ p01,
                                   const int* __restrict__ p12,
                                   int N0,
                                   const float* __restrict__ gg,
                                   const float* __restrict__ bb,
                                   float invN) {
    __shared__ float ws[8][32];
    __shared__ bool last;
    int lane = threadIdx.x & 31, wid = threadIdx.x >> 5;
#pragma unroll 1
    for (int srcId = 0; srcId < 3; srcId++) {
        const float* x = (srcId == 0) ? x0 : (srcId == 1) ? x1 : x2;
        float s[16], q[16];
#pragma unroll
        for (int c = 0; c < 16; c++) { s[c] = 0.0f; q[c] = 0.0f; }
        for (int i = blockIdx.x * blockDim.x + threadIdx.x; i < N0;
             i += gridDim.x * blockDim.x) {
            int r = i;
            if (srcId >= 1) r = __ldg(p01 + i);
            if (srcId == 2) r = __ldg(p12 + r);
            const float4* xr = (const float4*)(x + (size_t)r * 16);
#pragma unroll
            for (int t = 0; t < 4; t++) {
                float4 v = __ldg(xr + t);
                s[4 * t + 0] += v.x; q[4 * t + 0] += v.x * v.x;
                s[4 * t + 1] += v.y; q[4 * t + 1] += v.y * v.y;
                s[4 * t + 2] += v.z; q[4 * t + 2] += v.z * v.z;
                s[4 * t + 3] += v.w; q[4 * t + 3] += v.w * v.w;
            }
        }
#pragma unroll
        for (int c = 0; c < 16; c++) {
#pragma unroll
            for (int o = 16; o > 0; o >>= 1) {
                s[c] += __shfl_xor_sync(0xffffffffu, s[c], o);
                q[c] += __shfl_xor_sync(0xffffffffu, q[c], o);
            }
        }
        if (lane == 0) {
#pragma unroll
            for (int c = 0; c < 16; c++) { ws[wid][c] = s[c]; ws[wid][16 + c] = q[c]; }
        }
        __syncthreads();
        if (threadIdx.x < 32) {
            float v = 0.0f;
            int nw = blockDim.x >> 5;
            for (int w = 0; w < nw; w++) v += ws[w][threadIdx.x];
            int t = threadIdx.x;
            int off = srcId * 16;
            atomicAdd(&g_stats[(t < 16) ? (off + t) : (48 + off + t - 16)], v);
        }
        __syncthreads();
    }
    __threadfence();
    if (threadIdx.x == 0) {
        unsigned tk = atomicAdd(&g_ticket, 1u);
        last = (tk == (unsigned)gridDim.x - 1u);
    }
    __syncthreads();
    if (!last) return;
    if (threadIdx.x == 0) g_ticket = 0u;
    int t = threadIdx.x;
    if (t < 48) {
        float m = __ldcg(&g_stats[t]) * invN;
        float var = __ldcg(&g_stats[48 + t]) * invN - m * m;
        float sc = __ldg(gg + t) * rsqrtf(var + EPS);
        g_scale[t] = sc;
        g_shift[t] = __ldg(bb + t) - m * sc;
        g_stats[t] = 0.0f;
        g_stats[48 + t] = 0.0f;
    }
}

// ---------------------------------------------------------------------------
// Final: fused unpool-join (3x16 gather) + BN3-ReLU + SDF linear head.
// ---------------------------------------------------------------------------
__global__ void final_out_kernel(const float* __restrict__ x0,
                                 const float* __restrict__ x1,
                                 const float* __restrict__ x2,
                                 const int* __restrict__ p01,
                                 const int* __restrict__ p12,
                                 const float* __restrict__ wsdf,
                                 const float* __restrict__ bsdf,
                                 float* __restrict__ out, int N0) {
    __shared__ float sw[48], ssc[48], ssh[48];
    if (threadIdx.x < 48) {
        sw[threadIdx.x] = __ldg(wsdf + threadIdx.x);
        ssc[threadIdx.x] = g_scale[threadIdx.x];
        ssh[threadIdx.x] = g_shift[threadIdx.x];
    }
    __syncthreads();
    int i = blockIdx.x * blockDim.x + threadIdx.x;
    if (i >= N0) return;
    int p = __ldg(p01 + i);
    int qq = __ldg(p12 + p);
    float r = __ldg(bsdf);
    const float* rows[3] = { x0 + (size_t)i * 16, x1 + (size_t)p * 16,
                             x2 + (size_t)qq * 16 };
#pragma unroll
    for (int gidx = 0; gidx < 3; gidx++) {
        const float4* xr = (const float4*)rows[gidx];
#pragma unroll
        for (int t = 0; t < 4; t++) {
            float4 v = __ldg(xr + t);
            int c = gidx * 16 + t * 4;
            r += fmaxf(fmaf(v.x, ssc[c + 0], ssh[c + 0]), 0.0f) * sw[c + 0];
            r += fmaxf(fmaf(v.y, ssc[c + 1], ssh[c + 1]), 0.0f) * sw[c + 1];
            r += fmaxf(fmaf(v.z, ssc[c + 2], ssh[c + 2]), 0.0f) * sw[c + 2];
            r += fmaxf(fmaf(v.w, ssc[c + 3], ssh[c + 3]), 0.0f) * sw[c + 3];
        }
    }
    out[i] = r;
}

// ---------------------------------------------------------------------------
// Host orchestration
// ---------------------------------------------------------------------------
static inline int gdiv(int n, int t) { return (n + t - 1) / t; }
static inline int capg(int g) { return g < 1184 ? g : 1184; }

extern "C" void kernel_launch(void* const* d_in, const int* in_sizes, int n_in,
                              void* d_out, int out_size) {
    const float* feats = (const float*)d_in[0];
    const float* w_p1  = (const float*)d_in[1];
    const float* bn1g  = (const float*)d_in[2];
    const float* bn1b  = (const float*)d_in[3];
    const float* w1    = (const float*)d_in[4];
    const float* bn2g  = (const float*)d_in[5];
    const float* bn2b  = (const float*)d_in[6];
    const float* w2    = (const float*)d_in[7];
    const float* dbng  = (const float*)d_in[8];
    const float* dbnb  = (const float*)d_in[9];
    const float* dw    = (const float*)d_in[10];
    const float* bn3g  = (const float*)d_in[11];
    const float* bn3b  = (const float*)d_in[12];
    const float* wsdf  = (const float*)d_in[13];
    const float* bsdf  = (const float*)d_in[14];
    const int* nbr0    = (const int*)d_in[15];
    const int* nbr1    = (const int*)d_in[16];
    const int* nbr2    = (const int*)d_in[17];
    const int* down01  = (const int*)d_in[18];
    const int* down12  = (const int*)d_in[19];
    const int* p01     = (const int*)d_in[20];
    const int* p12     = (const int*)d_in[21];

    int N0 = in_sizes[0] / 2;
    int N1 = in_sizes[16] / 27;
    int N2 = in_sizes[17] / 27;

    float *X0, *X1, *X2, *T1, *T2;
    cudaGetSymbolAddress((void**)&X0, g_X0);
    cudaGetSymbolAddress((void**)&X1, g_X1);
    cudaGetSymbolAddress((void**)&X2, g_X2);
    cudaGetSymbolAddress((void**)&T1, g_T1);
    cudaGetSymbolAddress((void**)&T2, g_T2);

    const int T = 256;
    const int PG = 1184;
    const int G0 = capg(gdiv(N0, T)), G1 = capg(gdiv(N1, T)), G2 = capg(gdiv(N2, T));

    int B0 = gdiv(N0, T), B1 = gdiv(N1, T), B2 = gdiv(N2, T);
    int Bc0 = B0, Bc01 = B0 + B1, Bc012 = Bc01 + B2, Bc0123 = Bc012 + B1;
    int Ball = Bc0123 + B2;

    // ---- compaction (self offsets excluded; preloaded loads for MLP) ----
    zero_misc_kernel<<<1, 128>>>();
    count_all_kernel<<<Ball, T>>>(nbr0, nbr1, nbr2, down01, down12,
                                  N0, N1, N2, Bc0, Bc01, Bc012, Bc0123);
    scan_rows_kernel<<<97, 256>>>(gdiv(N0, 32), gdiv(N1, 32), gdiv(N2, 32),
                                  gdiv(N1, 32), gdiv(N2, 32));
    bucket_base_kernel<<<1, 160>>>();
    fill_all_kernel<<<Ball, T>>>(nbr0, nbr1, nbr2, down01, down12,
                                 N0, N1, N2, Bc0, Bc01, Bc012, Bc0123);

    // ---- level 0 ----
    init_p1_kernel<<<B0, T>>>(feats, w_p1, X0, N0);
    pairconv_p1_kernel<<<PG, T>>>(feats, w_p1, X0);                     // X0 = x

    reduce16_kernel<<<G0, T>>>(X0, N0, bn1g + 0, bn1b + 0, 1.0f / N0, 16);
    bnrelu_self_kernel<<<B0, T>>>(X0, T1, w1 + 0 * 6912 + 13 * 256, T2, 0, N0);
    pairconv16_kernel<27><<<PG, T>>>(RB0_P, 0, T1, w1 + 0 * 6912, T2);  // T2 = h1

    reduce16_kernel<<<G0, T>>>(T2, N0, bn2g + 0, bn2b + 0, 1.0f / N0, 16);
    bnrelu_self_kernel<<<B0, T>>>(T2, T1, w2 + 0 * 6912 + 13 * 256, X0, 1, N0);
    pairconv16_kernel<27><<<PG, T>>>(RB0_P, 0, T1, w2 + 0 * 6912, X0);  // X0 = r0

    reduce16_kernel<<<G0, T>>>(X0, N0, dbng + 0, dbnb + 0, 1.0f / N0, 16);
    bnrelu_zero_kernel<<<B0, T>>>(X0, T1, X1, N0, N1);
    pairconv16_kernel<8><<<PG, T>>>(RB3_P, 96, T1, dw + 0 * 2048, X1);  // X1 = y1

    // ---- level 1 ----
    reduce16_kernel<<<G1, T>>>(X1, N1, bn1g + 16, bn1b + 16, 1.0f / N1, 16);
    bnrelu_self_kernel<<<B1, T>>>(X1, T1, w1 + 1 * 6912 + 13 * 256, T2, 0, N1);
    pairconv16_kernel<27><<<PG, T>>>(RB1_P, 32, T1, w1 + 1 * 6912, T2);

    reduce16_kernel<<<G1, T>>>(T2, N1, bn2g + 16, bn2b + 16, 1.0f / N1, 16);
    bnrelu_self_kernel<<<B1, T>>>(T2, T1, w2 + 1 * 6912 + 13 * 256, X1, 1, N1);
    pairconv16_kernel<27><<<PG, T>>>(RB1_P, 32, T1, w2 + 1 * 6912, X1); // X1 = r1

    reduce16_kernel<<<G1, T>>>(X1, N1, dbng + 16, dbnb + 16, 1.0f / N1, 16);
    bnrelu_zero_kernel<<<B1, T>>>(X1, T1, X2, N1, N2);
    pairconv16_kernel<8><<<PG, T>>>(RB4_P, 128, T1, dw + 1 * 2048, X2); // X2 = z2

    // ---- level 2 ----
    reduce16_kernel<<<G2, T>>>(X2, N2, bn1g + 32, bn1b + 32, 1.0f / N2, 16);
    bnrelu_self_kernel<<<B2, T>>>(X2, T1, w1 + 2 * 6912 + 13 * 256, T2, 0, N2);
    pairconv16_kernel<27><<<PG, T>>>(RB2_P, 64, T1, w1 + 2 * 6912, T2);

    reduce16_kernel<<<G2, T>>>(T2, N2, bn2g + 32, bn2b + 32, 1.0f / N2, 16);
    bnrelu_self_kernel<<<B2, T>>>(T2, T1, w2 + 2 * 6912 + 13 * 256, X2, 1, N2);
    pairconv16_kernel<27><<<PG, T>>>(RB2_P, 64, T1, w2 + 2 * 6912, X2); // X2 = r2

    // ---- join + BN3 + SDF head ----
    reduce_join_kernel<<<G0, T>>>(X0, X1, X2, p01, p12, N0, bn3g, bn3b, 1.0f / N0);
    final_out_kernel<<<B0, T>>>(X0, X1, X2, p01, p12, wsdf, bsdf,
                                (float*)d_out, N0);
}

// round 13
// speedup vs baseline: 1.3373x; 1.1347x over previous
#include <cuda_runtime.h>
#include <cuda_fp16.h>

#define N0MAX 500000
#define WMAX  15680          // >= gdiv(N0MAX, 32)
#define EPS   1e-4f

// ---------------------------------------------------------------------------
// Scratch (device globals — no runtime allocation allowed)
// ---------------------------------------------------------------------------
__device__ float  g_X0[N0MAX * 16];
__device__ float  g_X1[N0MAX * 16];
__device__ float  g_X2[N0MAX * 16];
__device__ __half g_T1h[N0MAX * 16];   // bnrelu'd activations, fp16 (gather src)
__device__ float  g_T2[N0MAX * 16];
// flat pair lists per rulebook; pair = ((k<<20)|out_i, in_idx)
__device__ int2     g_pairs[(size_t)97 * N0MAX];
__device__ int      g_wcnt[160 * WMAX];   // per-(rb k, warp) counts -> bases
__device__ int      g_cnt[160];           // per-(rb k) totals
__device__ int      g_kbase[160];         // per-(rb k) flat base; [cbase+K]=total
__device__ float    g_stats[96];          // sum[0..47], sumsq[48..95]
__device__ float    g_scale[48];
__device__ float    g_shift[48];
__device__ unsigned g_ticket;

#define RB0_P ((size_t)0)
#define RB1_P ((size_t)27 * N0MAX)
#define RB2_P ((size_t)54 * N0MAX)
#define RB3_P ((size_t)81 * N0MAX)
#define RB4_P ((size_t)89 * N0MAX)

// ---------------------------------------------------------------------------
// f32x2 packed-math helpers (sm_103a FFMA2 — only reachable via PTX)
// ---------------------------------------------------------------------------
__device__ __forceinline__ unsigned long long fma2(unsigned long long a,
                                                   unsigned long long b,
                                                   unsigned long long c) {
    unsigned long long d;
    asm("fma.rn.f32x2 %0, %1, %2, %3;" : "=l"(d) : "l"(a), "l"(b), "l"(c));
    return d;
}
__device__ __forceinline__ unsigned long long dup2(float v) {
    unsigned long long d;
    asm("mov.b64 %0, {%1, %1};" : "=l"(d) : "f"(v));
    return d;
}
__device__ __forceinline__ float2 up2(unsigned long long v) {
    float2 f;
    asm("mov.b64 {%0, %1}, %2;" : "=f"(f.x), "=f"(f.y) : "l"(v));
    return f;
}
__device__ __forceinline__ void red4(float* p, float4 v) {
    asm volatile("red.global.add.v4.f32 [%0], {%1, %2, %3, %4};"
                 :: "l"(p), "f"(v.x), "f"(v.y), "f"(v.z), "f"(v.w) : "memory");
}

#define JSTEP2(Wk, jj, yv, a0, a1, a2, a3, a4, a5, a6, a7) { \
    unsigned long long yy = dup2(yv); \
    ulonglong2 p0 = (Wk)[4*(jj)+0], p1 = (Wk)[4*(jj)+1]; \
    ulonglong2 p2 = (Wk)[4*(jj)+2], p3 = (Wk)[4*(jj)+3]; \
    a0 = fma2(yy, p0.x, a0); a1 = fma2(yy, p0.y, a1); \
    a2 = fma2(yy, p1.x, a2); a3 = fma2(yy, p1.y, a3); \
    a4 = fma2(yy, p2.x, a4); a5 = fma2(yy, p2.y, a5); \
    a6 = fma2(yy, p3.x, a6); a7 = fma2(yy, p3.y, a7); }

#define JSTEP16(Wk, y0, y1, y2, y3, a0, a1, a2, a3, a4, a5, a6, a7) \
    JSTEP2(Wk, 0,  y0.x, a0,a1,a2,a3,a4,a5,a6,a7) \
    JSTEP2(Wk, 1,  y0.y, a0,a1,a2,a3,a4,a5,a6,a7) \
    JSTEP2(Wk, 2,  y0.z, a0,a1,a2,a3,a4,a5,a6,a7) \
    JSTEP2(Wk, 3,  y0.w, a0,a1,a2,a3,a4,a5,a6,a7) \
    JSTEP2(Wk, 4,  y1.x, a0,a1,a2,a3,a4,a5,a6,a7) \
    JSTEP2(Wk, 5,  y1.y, a0,a1,a2,a3,a4,a5,a6,a7) \
    JSTEP2(Wk, 6,  y1.z, a0,a1,a2,a3,a4,a5,a6,a7) \
    JSTEP2(Wk, 7,  y1.w, a0,a1,a2,a3,a4,a5,a6,a7) \
    JSTEP2(Wk, 8,  y2.x, a0,a1,a2,a3,a4,a5,a6,a7) \
    JSTEP2(Wk, 9,  y2.y, a0,a1,a2,a3,a4,a5,a6,a7) \
    JSTEP2(Wk, 10, y2.z, a0,a1,a2,a3,a4,a5,a6,a7) \
    JSTEP2(Wk, 11, y2.w, a0,a1,a2,a3,a4,a5,a6,a7) \
    JSTEP2(Wk, 12, y3.x, a0,a1,a2,a3,a4,a5,a6,a7) \
    JSTEP2(Wk, 13, y3.y, a0,a1,a2,a3,a4,a5,a6,a7) \
    JSTEP2(Wk, 14, y3.z, a0,a1,a2,a3,a4,a5,a6,a7) \
    JSTEP2(Wk, 15, y3.w, a0,a1,a2,a3,a4,a5,a6,a7)

// store 16 fp32 values as 16 fp16 (two uint4 = 32B) at row i of T1h
__device__ __forceinline__ void store_half_row(__half* base, size_t i,
                                               const float* v) {
    __half2 h[8];
#pragma unroll
    for (int t = 0; t < 8; t++) h[t] = __floats2half2_rn(v[2 * t], v[2 * t + 1]);
    uint4* yr = (uint4*)(base + i * 16);
    yr[0] = *(uint4*)&h[0];
    yr[1] = *(uint4*)&h[4];
}

// ---------------------------------------------------------------------------
__global__ void zero_misc_kernel() {
    int t = threadIdx.x;
    if (t < 96) g_stats[t] = 0.0f;
    if (t == 0) g_ticket = 0u;
}

// ---------------------------------------------------------------------------
// Compaction phase 1: per-(k, warp) active counts. PRELOADED nbr reads
// (registers, MLP~K). k==13 excluded for K=27 rulebooks.
// ---------------------------------------------------------------------------
template <int K>
__device__ __forceinline__ void count_dev(const int* __restrict__ nbr,
                                          int Nout, int Nin, int cbase, int lb) {
    int i = lb * 256 + threadIdx.x;
    bool inb = i < Nout;
    int lane = threadIdx.x & 31;
    int w = i >> 5;
    int idx[K];
#pragma unroll
    for (int k = 0; k < K; k++)
        idx[k] = inb ? __ldg(nbr + (size_t)k * Nout + i) : Nin;
#pragma unroll
    for (int k = 0; k < K; k++) {
        if (K == 27 && k == 13) continue;
        unsigned m = __ballot_sync(0xffffffffu, idx[k] < Nin);
        if (lane == 0) g_wcnt[(size_t)(cbase + k) * WMAX + w] = __popc(m);
    }
}

__global__ void count_all_kernel(const int* nbr0, const int* nbr1,
                                 const int* nbr2, const int* d01,
                                 const int* d12, int N0, int N1, int N2,
                                 int B0, int B01, int B012, int B0123) {
    int b = blockIdx.x;
    if (b < B0)           count_dev<27>(nbr0, N0, N0, 0,   b);
    else if (b < B01)     count_dev<27>(nbr1, N1, N1, 32,  b - B0);
    else if (b < B012)    count_dev<27>(nbr2, N2, N2, 64,  b - B01);
    else if (b < B0123)   count_dev<8> (d01,  N1, N0, 96,  b - B012);
    else                  count_dev<8> (d12,  N2, N1, 128, b - B0123);
}

// ---------------------------------------------------------------------------
// Compaction phase 2: exclusive scan per (rb, k) row; one block per row.
// ---------------------------------------------------------------------------
__global__ void scan_rows_kernel(int nw0, int nw1, int nw2, int nw3, int nw4) {
    int b = blockIdx.x;
    int row, nw;
    if (b < 27)      { row = b;            nw = nw0; }
    else if (b < 54) { row = 32 + b - 27;  nw = nw1; }
    else if (b < 81) { row = 64 + b - 54;  nw = nw2; }
    else if (b < 89) { row = 96 + b - 81;  nw = nw3; }
    else             { row = 128 + b - 89; nw = nw4; }
    if (row == 13 || row == 45 || row == 77) {
        if (threadIdx.x == 0) g_cnt[row] = 0;
        return;
    }
    int* p = g_wcnt + (size_t)row * WMAX;
    int t = threadIdx.x, lane = t & 31, wid = t >> 5;
    __shared__ int wtot[8];
    __shared__ int carry;
    if (t == 0) carry = 0;
    __syncthreads();
    for (int base = 0; base < nw; base += 256) {
        int v = (base + t < nw) ? p[base + t] : 0;
        int x = v;
#pragma unroll
        for (int off = 1; off < 32; off <<= 1) {
            int yv = __shfl_up_sync(0xffffffffu, x, off);
            if (lane >= off) x += yv;
        }
        if (lane == 31) wtot[wid] = x;
        __syncthreads();
        int wofs = 0;
#pragma unroll
        for (int w2 = 0; w2 < 8; w2++) wofs += (w2 < wid) ? wtot[w2] : 0;
        if (base + t < nw) p[base + t] = x - v + wofs + carry;
        __syncthreads();
        if (t == 0) {
            int s = 0;
#pragma unroll
            for (int w2 = 0; w2 < 8; w2++) s += wtot[w2];
            carry += s;
        }
        __syncthreads();
    }
    if (t == 0) g_cnt[row] = carry;
}

// Per-rb exclusive scan over k -> flat bucket bases + totals (1 warp per rb).
__global__ void bucket_base_kernel() {
    int wid = threadIdx.x >> 5;
    int lane = threadIdx.x & 31;
    if (wid >= 5) return;
    const int cb[5] = {0, 32, 64, 96, 128};
    const int kk[5] = {27, 27, 27, 8, 8};
    int K = kk[wid], base = cb[wid];
    int v = (lane < K) ? __ldg(&g_cnt[base + lane]) : 0;
    int x = v;
#pragma unroll
    for (int off = 1; off < 32; off <<= 1) {
        int yv = __shfl_up_sync(0xffffffffu, x, off);
        if (lane >= off) x += yv;
    }
    if (lane < K) g_kbase[base + lane] = x - v;
    int tot = __shfl_sync(0xffffffffu, x, K - 1);
    if (lane == K) g_kbase[base + K] = tot;
}

// ---------------------------------------------------------------------------
// Compaction phase 3: PRELOADED fill; write pairs at flat slots; skip k==13.
// ---------------------------------------------------------------------------
template <int K>
__device__ __forceinline__ void fill_dev(const int* __restrict__ nbr,
                                         int Nout, int Nin, int cbase,
                                         size_t pbase, int lb) {
    int i = lb * 256 + threadIdx.x;
    bool inb = i < Nout;
    int lane = threadIdx.x & 31;
    int w = i >> 5;
    unsigned lt = (1u << lane) - 1u;
    int idx[K];
#pragma unroll
    for (int k = 0; k < K; k++)
        idx[k] = inb ? __ldg(nbr + (size_t)k * Nout + i) : Nin;
#pragma unroll
    for (int k = 0; k < K; k++) {
        if (K == 27 && k == 13) continue;
        bool act = idx[k] < Nin;
        unsigned m = __ballot_sync(0xffffffffu, act);
        if (!m) continue;
        int base = __ldg(&g_kbase[cbase + k]) +
                   __ldg(&g_wcnt[(size_t)(cbase + k) * WMAX + w]);
        if (act)
            g_pairs[pbase + base + __popc(m & lt)] =
                make_int2((k << 20) | i, idx[k]);
    }
}

__global__ void fill_all_kernel(const int* nbr0, const int* nbr1,
                                const int* nbr2, const int* d01,
                                const int* d12, int N0, int N1, int N2,
                                int B0, int B01, int B012, int B0123) {
    int b = blockIdx.x;
    if (b < B0)           fill_dev<27>(nbr0, N0, N0, 0,   RB0_P, b);
    else if (b < B01)     fill_dev<27>(nbr1, N1, N1, 32,  RB1_P, b - B0);
    else if (b < B012)    fill_dev<27>(nbr2, N2, N2, 64,  RB2_P, b - B01);
    else if (b < B0123)   fill_dev<8> (d01,  N1, N0, 96,  RB3_P, b - B012);
    else                  fill_dev<8> (d12,  N2, N1, 128, RB4_P, b - B0123);
}

// ---------------------------------------------------------------------------
// Pair-parallel sparse conv 16->16 (non-self offsets only), FFMA2 packed.
// y buffer is FP16 (32B/row gather, half the traffic); weights/accum fp32.
// k warp-uniform within a bucket -> broadcast LDS.128 W reads.
// red.global.add.v4 scatter into pre-initialized target.
// ---------------------------------------------------------------------------
template <int K>
__global__ void pairconv16_kernel(size_t pbase, int cbase,
                                  const __half* __restrict__ y,
                                  const float* __restrict__ Wg,  // [K,16,16]
                                  float* __restrict__ out) {
    __shared__ float4 Ws[K * 64];
    __shared__ int sP;
    if (threadIdx.x == 0) sP = g_kbase[cbase + K];
    __syncthreads();
    int P = sP;
    if (blockIdx.x * blockDim.x >= P) return;
    for (int t = threadIdx.x; t < K * 64; t += blockDim.x)
        Ws[t] = __ldg((const float4*)Wg + t);
    __syncthreads();

    for (int t = blockIdx.x * blockDim.x + threadIdx.x; t < P;
         t += gridDim.x * blockDim.x) {
        int2 pr = __ldg(&g_pairs[pbase + t]);
        int k = pr.x >> 20;
        int oi = pr.x & 0xFFFFF;
        const uint4* yr = (const uint4*)(y + (size_t)pr.y * 16);
        uint4 ha = __ldg(yr + 0), hb = __ldg(yr + 1);
        const __half2* hpa = (const __half2*)&ha;
        const __half2* hpb = (const __half2*)&hb;
        float2 c0 = __half22float2(hpa[0]), c1 = __half22float2(hpa[1]);
        float2 c2 = __half22float2(hpa[2]), c3 = __half22float2(hpa[3]);
        float2 c4 = __half22float2(hpb[0]), c5 = __half22float2(hpb[1]);
        float2 c6 = __half22float2(hpb[2]), c7 = __half22float2(hpb[3]);
        float4 y0 = make_float4(c0.x, c0.y, c1.x, c1.y);
        float4 y1 = make_float4(c2.x, c2.y, c3.x, c3.y);
        float4 y2 = make_float4(c4.x, c4.y, c5.x, c5.y);
        float4 y3 = make_float4(c6.x, c6.y, c7.x, c7.y);
        const ulonglong2* Wk = (const ulonglong2*)(Ws + (size_t)k * 64);
        unsigned long long a0 = 0, a1 = 0, a2 = 0, a3 = 0,
                           a4 = 0, a5 = 0, a6 = 0, a7 = 0;
        JSTEP16(Wk, y0, y1, y2, y3, a0, a1, a2, a3, a4, a5, a6, a7)

        float* op = out + (size_t)oi * 16;
        float2 f0 = up2(a0), f1 = up2(a1), f2 = up2(a2), f3 = up2(a3);
        float2 f4 = up2(a4), f5 = up2(a5), f6 = up2(a6), f7 = up2(a7);
        red4(op + 0,  make_float4(f0.x, f0.y, f1.x, f1.y));
        red4(op + 4,  make_float4(f2.x, f2.y, f3.x, f3.y));
        red4(op + 8,  make_float4(f4.x, f4.y, f5.x, f5.y));
        red4(op + 12, make_float4(f6.x, f6.y, f7.x, f7.y));
    }
}

// p1 pair conv: Cin=2 -> 16, non-self rb0 pairs, raw fp32 feats
__global__ void pairconv_p1_kernel(const float* __restrict__ feats,
                                   const float* __restrict__ Wg,  // [27,2,16]
                                   float* __restrict__ out) {
    __shared__ float4 Ws[27 * 8];
    __shared__ int sP;
    if (threadIdx.x == 0) sP = g_kbase[27];
    __syncthreads();
    int P = sP;
    if (blockIdx.x * blockDim.x >= P) return;
    for (int t = threadIdx.x; t < 27 * 8; t += blockDim.x)
        Ws[t] = __ldg((const float4*)Wg + t);
    __syncthreads();

    for (int t = blockIdx.x * blockDim.x + threadIdx.x; t < P;
         t += gridDim.x * blockDim.x) {
        int2 pr = __ldg(&g_pairs[RB0_P + t]);
        int k = pr.x >> 20;
        int oi = pr.x & 0xFFFFF;
        float2 f = __ldg((const float2*)(feats + (size_t)pr.y * 2));
        const float4* Wk = &Ws[k * 8];
        float4 u0 = Wk[0], u1 = Wk[1], u2 = Wk[2], u3 = Wk[3];
        float4 v0 = Wk[4], v1 = Wk[5], v2 = Wk[6], v3 = Wk[7];
        float4 a0 = make_float4(fmaf(f.y, v0.x, f.x * u0.x), fmaf(f.y, v0.y, f.x * u0.y),
                                fmaf(f.y, v0.z, f.x * u0.z), fmaf(f.y, v0.w, f.x * u0.w));
        float4 a1 = make_float4(fmaf(f.y, v1.x, f.x * u1.x), fmaf(f.y, v1.y, f.x * u1.y),
                                fmaf(f.y, v1.z, f.x * u1.z), fmaf(f.y, v1.w, f.x * u1.w));
        float4 a2 = make_float4(fmaf(f.y, v2.x, f.x * u2.x), fmaf(f.y, v2.y, f.x * u2.y),
                                fmaf(f.y, v2.z, f.x * u2.z), fmaf(f.y, v2.w, f.x * u2.w));
        float4 a3 = make_float4(fmaf(f.y, v3.x, f.x * u3.x), fmaf(f.y, v3.y, f.x * u3.y),
                                fmaf(f.y, v3.z, f.x * u3.z), fmaf(f.y, v3.w, f.x * u3.w));
        float* op = out + (size_t)oi * 16;
        red4(op + 0, a0); red4(op + 4, a1); red4(op + 8, a2); red4(op + 12, a3);
    }
}

// p1 self init: X0[i] = feats[i] . W_p1[13]  (dense, replaces memset)
__global__ void init_p1_kernel(const float* __restrict__ feats,
                               const float* __restrict__ Wg,  // [27,2,16]
                               float* __restrict__ out, int N) {
    __shared__ float4 Ws[8];
    if (threadIdx.x < 8) Ws[threadIdx.x] = __ldg((const float4*)Wg + 13 * 8 + threadIdx.x);
    __syncthreads();
    int i = blockIdx.x * blockDim.x + threadIdx.x;
    if (i >= N) return;
    float2 f = __ldg((const float2*)(feats + (size_t)i * 2));
    float4* o = (float4*)(out + (size_t)i * 16);
#pragma unroll
    for (int q = 0; q < 4; q++) {
        float4 u = Ws[q], v = Ws[4 + q];
        o[q] = make_float4(fmaf(f.y, v.x, f.x * u.x), fmaf(f.y, v.y, f.x * u.y),
                           fmaf(f.y, v.z, f.x * u.z), fmaf(f.y, v.w, f.x * u.w));
    }
}

// ---------------------------------------------------------------------------
// bnrelu + self-contribution init: y(fp16) = relu(x*scale+shift);
// target[i] = Wself^T y_fp32 (+ target[i] if addTo). Self term stays fp32.
// ---------------------------------------------------------------------------
__global__ void bnrelu_self_kernel(const float* __restrict__ x,
                                   __half* __restrict__ y,
                                   const float* __restrict__ Wself, // [16,16]
                                   float* __restrict__ target,
                                   int addTo, int N) {
    __shared__ float4 Ws[64];
    if (threadIdx.x < 64) Ws[threadIdx.x] = __ldg((const float4*)Wself + threadIdx.x);
    __syncthreads();
    int i = blockIdx.x * blockDim.x + threadIdx.x;
    if (i >= N) return;
    const float4* xr = (const float4*)(x + (size_t)i * 16);
    float v[16];
#pragma unroll
    for (int q = 0; q < 4; q++) {
        float4 t = __ldg(xr + q);
        v[4 * q + 0] = fmaxf(fmaf(t.x, g_scale[4 * q + 0], g_shift[4 * q + 0]), 0.f);
        v[4 * q + 1] = fmaxf(fmaf(t.y, g_scale[4 * q + 1], g_shift[4 * q + 1]), 0.f);
        v[4 * q + 2] = fmaxf(fmaf(t.z, g_scale[4 * q + 2], g_shift[4 * q + 2]), 0.f);
        v[4 * q + 3] = fmaxf(fmaf(t.w, g_scale[4 * q + 3], g_shift[4 * q + 3]), 0.f);
    }
    store_half_row(y, (size_t)i, v);
    float4 a0 = make_float4(0.f, 0.f, 0.f, 0.f), a1 = a0, a2 = a0, a3 = a0;
#pragma unroll
    for (int j = 0; j < 16; j++) {
        float yv = v[j];
        float4 w0 = Ws[4 * j + 0], w1 = Ws[4 * j + 1];
        float4 w2 = Ws[4 * j + 2], w3 = Ws[4 * j + 3];
        a0.x = fmaf(yv, w0.x, a0.x); a0.y = fmaf(yv, w0.y, a0.y);
        a0.z = fmaf(yv, w0.z, a0.z); a0.w = fmaf(yv, w0.w, a0.w);
        a1.x = fmaf(yv, w1.x, a1.x); a1.y = fmaf(yv, w1.y, a1.y);
        a1.z = fmaf(yv, w1.z, a1.z); a1.w = fmaf(yv, w1.w, a1.w);
        a2.x = fmaf(yv, w2.x, a2.x); a2.y = fmaf(yv, w2.y, a2.y);
        a2.z = fmaf(yv, w2.z, a2.z); a2.w = fmaf(yv, w2.w, a2.w);
        a3.x = fmaf(yv, w3.x, a3.x); a3.y = fmaf(yv, w3.y, a3.y);
        a3.z = fmaf(yv, w3.z, a3.z); a3.w = fmaf(yv, w3.w, a3.w);
    }
    float4* tg = (float4*)(target + (size_t)i * 16);
    if (addTo) {
        float4 r0 = tg[0], r1 = tg[1], r2 = tg[2], r3 = tg[3];
        a0.x += r0.x; a0.y += r0.y; a0.z += r0.z; a0.w += r0.w;
        a1.x += r1.x; a1.y += r1.y; a1.z += r1.z; a1.w += r1.w;
        a2.x += r2.x; a2.y += r2.y; a2.z += r2.z; a2.w += r2.w;
        a3.x += r3.x; a3.y += r3.y; a3.z += r3.z; a3.w += r3.w;
    }
    tg[0] = a0; tg[1] = a1; tg[2] = a2; tg[3] = a3;
}

// bnrelu (fp16 y) + zero-init of a (different-sized) downsample target
__global__ void bnrelu_zero_kernel(const float* __restrict__ x,
                                   __half* __restrict__ y,
                                   float* __restrict__ zb, int N, int Nz) {
    int i = blockIdx.x * blockDim.x + threadIdx.x;
    if (i < N) {
        const float4* xr = (const float4*)(x + (size_t)i * 16);
        float v[16];
#pragma unroll
        for (int q = 0; q < 4; q++) {
            float4 t = __ldg(xr + q);
            v[4 * q + 0] = fmaxf(fmaf(t.x, g_scale[4 * q + 0], g_shift[4 * q + 0]), 0.f);
            v[4 * q + 1] = fmaxf(fmaf(t.y, g_scale[4 * q + 1], g_shift[4 * q + 1]), 0.f);
            v[4 * q + 2] = fmaxf(fmaf(t.z, g_scale[4 * q + 2], g_shift[4 * q + 2]), 0.f);
            v[4 * q + 3] = fmaxf(fmaf(t.w, g_scale[4 * q + 3], g_shift[4 * q + 3]), 0.f);
        }
        store_half_row(y, (size_t)i, v);
    }
    if (i < Nz) {
        float4* zr = (float4*)(zb + (size_t)i * 16);
        float4 z = make_float4(0.f, 0.f, 0.f, 0.f);
        zr[0] = z; zr[1] = z; zr[2] = z; zr[3] = z;
    }
}

// ---------------------------------------------------------------------------
// Per-channel sum/sumsq over N rows with BN finalize in last block (Cfin>0).
// ---------------------------------------------------------------------------
__global__ void reduce16_kernel(const float* __restrict__ x, int N,
                                const float* __restrict__ gg,
                                const float* __restrict__ bb,
                                float invN, int Cfin) {
    float s[16], q[16];
#pragma unroll
    for (int c = 0; c < 16; c++) { s[c] = 0.0f; q[c] = 0.0f; }
    for (int i = blockIdx.x * blockDim.x + threadIdx.x; i < N;
         i += gridDim.x * blockDim.x) {
        const float4* xr = (const float4*)(x + (size_t)i * 16);
#pragma unroll
        for (int t = 0; t < 4; t++) {
            float4 v = __ldg(xr + t);
            s[4 * t + 0] += v.x; q[4 * t + 0] += v.x * v.x;
            s[4 * t + 1] += v.y; q[4 * t + 1] += v.y * v.y;
            s[4 * t + 2] += v.z; q[4 * t + 2] += v.z * v.z;
            s[4 * t + 3] += v.w; q[4 * t + 3] += v.w * v.w;
        }
    }
#pragma unroll
    for (int c = 0; c < 16; c++) {
#pragma unroll
        for (int o = 16; o > 0; o >>= 1) {
            s[c] += __shfl_xor_sync(0xffffffffu, s[c], o);
            q[c] += __shfl_xor_sync(0xffffffffu, q[c], o);
        }
    }
    __shared__ float ws[8][32];
    __shared__ bool last;
    int lane = threadIdx.x & 31, wid = threadIdx.x >> 5;
    if (lane == 0) {
#pragma unroll
        for (int c = 0; c < 16; c++) { ws[wid][c] = s[c]; ws[wid][16 + c] = q[c]; }
    }
    __syncthreads();
    if (threadIdx.x < 32) {
        float v = 0.0f;
        int nw = blockDim.x >> 5;
        for (int w = 0; w < nw; w++) v += ws[w][threadIdx.x];
        int t = threadIdx.x;
        atomicAdd(&g_stats[(t < 16) ? t : (48 + t - 16)], v);
    }
    __threadfence();
    if (threadIdx.x == 0) {
        unsigned tk = atomicAdd(&g_ticket, 1u);
        last = (tk == (unsigned)gridDim.x - 1u);
    }
    __syncthreads();
    if (!last) return;
    if (threadIdx.x == 0) g_ticket = 0u;
    int t = threadIdx.x;
    if (t < Cfin) {
        float m = __ldcg(&g_stats[t]) * invN;
        float var = __ldcg(&g_stats[48 + t]) * invN - m * m;
        float sc = __ldg(gg + t) * rsqrtf(var + EPS);
        g_scale[t] = sc;
        g_shift[t] = __ldg(bb + t) - m * sc;
        g_stats[t] = 0.0f;
        g_stats[48 + t] = 0.0f;
    }
}

// ---------------------------------------------------------------------------
// Join stats: 3 sources (x0 direct; x1 via p01; x2 via p01->p12), 48 channels,
// finalize fused into last block.
// ---------------------------------------------------------------------------
__global__ void reduce_join_kernel(const float* __restrict__ x0,
                                   const float* __restrict__ x1,
                                   const float* __restrict__ x2,
                                   const int* __restrict__ p01,
                                   const int* __restrict__ p12,
                                   int N0,
                                   const float* __restrict__ gg,
                                   const float* __restrict__ bb,
                                   float invN) {
    __shared__ float ws[8][32];
    __shared__ bool last;
    int lane = threadIdx.x & 31, wid = threadIdx.x >> 5;
#pragma unroll 1
    for (int srcId = 0; srcId < 3; srcId++) {
        const float* x = (srcId == 0) ? x0 : (srcId == 1) ? x1 : x2;
        float s[16], q[16];
#pragma unroll
        for (int c = 0; c < 16; c++) { s[c] = 0.0f; q[c] = 0.0f; }
        for (int i = blockIdx.x * blockDim.x + threadIdx.x; i < N0;
             i += gridDim.x * blockDim.x) {
            int r = i;
            if (srcId >= 1) r = __ldg(p01 + i);
            if (srcId == 2) r = __ldg(p12 + r);
            const float4* xr = (const float4*)(x + (size_t)r * 16);
#pragma unroll
            for (int t = 0; t < 4; t++) {
                float4 v = __ldg(xr + t);
                s[4 * t + 0] += v.x; q[4 * t + 0] += v.x * v.x;
                s[4 * t + 1] += v.y; q[4 * t + 1] += v.y * v.y;
                s[4 * t + 2] += v.z; q[4 * t + 2] += v.z * v.z;
                s[4 * t + 3] += v.w; q[4 * t + 3] += v.w * v.w;
            }
        }
#pragma unroll
        for (int c = 0; c < 16; c++) {
#pragma unroll
            for (int o = 16; o > 0; o >>= 1) {
                s[c] += __shfl_xor_sync(0xffffffffu, s[c], o);
                q[c] += __shfl_xor_sync(0xffffffffu, q[c], o);
            }
        }
        if (lane == 0) {
#pragma unroll
            for (int c = 0; c < 16; c++) { ws[wid][c] = s[c]; ws[wid][16 + c] = q[c]; }
        }
        __syncthreads();
        if (threadIdx.x < 32) {
            float v = 0.0f;
            int nw = blockDim.x >> 5;
            for (int w = 0; w < nw; w++) v += ws[w][threadIdx.x];
            int t = threadIdx.x;
            int off = srcId * 16;
            atomicAdd(&g_stats[(t < 16) ? (off + t) : (48 + off + t - 16)], v);
        }
        __syncthreads();
    }
    __threadfence();
    if (threadIdx.x == 0) {
        unsigned tk = atomicAdd(&g_ticket, 1u);
        last = (tk == (unsigned)gridDim.x - 1u);
    }
    __syncthreads();
    if (!last) return;
    if (threadIdx.x == 0) g_ticket = 0u;
    int t = threadIdx.x;
    if (t < 48) {
        float m = __ldcg(&g_stats[t]) * invN;
        float var = __ldcg(&g_stats[48 + t]) * invN - m * m;
        float sc = __ldg(gg + t) * rsqrtf(var + EPS);
        g_scale[t] = sc;
        g_shift[t] = __ldg(bb + t) - m * sc;
        g_stats[t] = 0.0f;
        g_stats[48 + t] = 0.0f;
    }
}

// ---------------------------------------------------------------------------
// Final: fused unpool-join (3x16 gather) + BN3-ReLU + SDF linear head.
// ---------------------------------------------------------------------------
__global__ void final_out_kernel(const float* __restrict__ x0,
                                 const float* __restrict__ x1,
                                 const float* __restrict__ x2,
                                 const int* __restrict__ p01,
                                 const int* __restrict__ p12,
                                 const float* __restrict__ wsdf,
                                 const float* __restrict__ bsdf,
                                 float* __restrict__ out, int N0) {
    __shared__ float sw[48], ssc[48], ssh[48];
    if (threadIdx.x < 48) {
        sw[threadIdx.x] = __ldg(wsdf + threadIdx.x);
        ssc[threadIdx.x] = g_scale[threadIdx.x];
        ssh[threadIdx.x] = g_shift[threadIdx.x];
    }
    __syncthreads();
    int i = blockIdx.x * blockDim.x + threadIdx.x;
    if (i >= N0) return;
    int p = __ldg(p01 + i);
    int qq = __ldg(p12 + p);
    float r = __ldg(bsdf);
    const float* rows[3] = { x0 + (size_t)i * 16, x1 + (size_t)p * 16,
                             x2 + (size_t)qq * 16 };
#pragma unroll
    for (int gidx = 0; gidx < 3; gidx++) {
        const float4* xr = (const float4*)rows[gidx];
#pragma unroll
        for (int t = 0; t < 4; t++) {
            float4 v = __ldg(xr + t);
            int c = gidx * 16 + t * 4;
            r += fmaxf(fmaf(v.x, ssc[c + 0], ssh[c + 0]), 0.0f) * sw[c + 0];
            r += fmaxf(fmaf(v.y, ssc[c + 1], ssh[c + 1]), 0.0f) * sw[c + 1];
            r += fmaxf(fmaf(v.z, ssc[c + 2], ssh[c + 2]), 0.0f) * sw[c + 2];
            r += fmaxf(fmaf(v.w, ssc[c + 3], ssh[c + 3]), 0.0f) * sw[c + 3];
        }
    }
    out[i] = r;
}

// ---------------------------------------------------------------------------
// Host orchestration
// ---------------------------------------------------------------------------
static inline int gdiv(int n, int t) { return (n + t - 1) / t; }
static inline int capg(int g) { return g < 1184 ? g : 1184; }

extern "C" void kernel_launch(void* const* d_in, const int* in_sizes, int n_in,
                              void* d_out, int out_size) {
    const float* feats = (const float*)d_in[0];
    const float* w_p1  = (const float*)d_in[1];
    const float* bn1g  = (const float*)d_in[2];
    const float* bn1b  = (const float*)d_in[3];
    const float* w1    = (const float*)d_in[4];
    const float* bn2g  = (const float*)d_in[5];
    const float* bn2b  = (const float*)d_in[6];
    const float* w2    = (const float*)d_in[7];
    const float* dbng  = (const float*)d_in[8];
    const float* dbnb  = (const float*)d_in[9];
    const float* dw    = (const float*)d_in[10];
    const float* bn3g  = (const float*)d_in[11];
    const float* bn3b  = (const float*)d_in[12];
    const float* wsdf  = (const float*)d_in[13];
    const float* bsdf  = (const float*)d_in[14];
    const int* nbr0    = (const int*)d_in[15];
    const int* nbr1    = (const int*)d_in[16];
    const int* nbr2    = (const int*)d_in[17];
    const int* down01  = (const int*)d_in[18];
    const int* down12  = (const int*)d_in[19];
    const int* p01     = (const int*)d_in[20];
    const int* p12     = (const int*)d_in[21];

    int N0 = in_sizes[0] / 2;
    int N1 = in_sizes[16] / 27;
    int N2 = in_sizes[17] / 27;

    float *X0, *X1, *X2, *T2;
    __half* T1;
    cudaGetSymbolAddress((void**)&X0, g_X0);
    cudaGetSymbolAddress((void**)&X1, g_X1);
    cudaGetSymbolAddress((void**)&X2, g_X2);
    cudaGetSymbolAddress((void**)&T1, g_T1h);
    cudaGetSymbolAddress((void**)&T2, g_T2);

    const int T = 256;
    const int PG = 1184;
    const int G0 = capg(gdiv(N0, T)), G1 = capg(gdiv(N1, T)), G2 = capg(gdiv(N2, T));

    int B0 = gdiv(N0, T), B1 = gdiv(N1, T), B2 = gdiv(N2, T);
    int Bc0 = B0, Bc01 = B0 + B1, Bc012 = Bc01 + B2, Bc0123 = Bc012 + B1;
    int Ball = Bc0123 + B2;

    // ---- compaction (self offsets excluded; preloaded loads for MLP) ----
    zero_misc_kernel<<<1, 128>>>();
    count_all_kernel<<<Ball, T>>>(nbr0, nbr1, nbr2, down01, down12,
                                  N0, N1, N2, Bc0, Bc01, Bc012, Bc0123);
    scan_rows_kernel<<<97, 256>>>(gdiv(N0, 32), gdiv(N1, 32), gdiv(N2, 32),
                                  gdiv(N1, 32), gdiv(N2, 32));
    bucket_base_kernel<<<1, 160>>>();
    fill_all_kernel<<<Ball, T>>>(nbr0, nbr1, nbr2, down01, down12,
                                 N0, N1, N2, Bc0, Bc01, Bc012, Bc0123);

    // ---- level 0 ----
    init_p1_kernel<<<B0, T>>>(feats, w_p1, X0, N0);
    pairconv_p1_kernel<<<PG, T>>>(feats, w_p1, X0);                     // X0 = x

    reduce16_kernel<<<G0, T>>>(X0, N0, bn1g + 0, bn1b + 0, 1.0f / N0, 16);
    bnrelu_self_kernel<<<B0, T>>>(X0, T1, w1 + 0 * 6912 + 13 * 256, T2, 0, N0);
    pairconv16_kernel<27><<<PG, T>>>(RB0_P, 0, T1, w1 + 0 * 6912, T2);  // T2 = h1

    reduce16_kernel<<<G0, T>>>(T2, N0, bn2g + 0, bn2b + 0, 1.0f / N0, 16);
    bnrelu_self_kernel<<<B0, T>>>(T2, T1, w2 + 0 * 6912 + 13 * 256, X0, 1, N0);
    pairconv16_kernel<27><<<PG, T>>>(RB0_P, 0, T1, w2 + 0 * 6912, X0);  // X0 = r0

    reduce16_kernel<<<G0, T>>>(X0, N0, dbng + 0, dbnb + 0, 1.0f / N0, 16);
    bnrelu_zero_kernel<<<B0, T>>>(X0, T1, X1, N0, N1);
    pairconv16_kernel<8><<<PG, T>>>(RB3_P, 96, T1, dw + 0 * 2048, X1);  // X1 = y1

    // ---- level 1 ----
    reduce16_kernel<<<G1, T>>>(X1, N1, bn1g + 16, bn1b + 16, 1.0f / N1, 16);
    bnrelu_self_kernel<<<B1, T>>>(X1, T1, w1 + 1 * 6912 + 13 * 256, T2, 0, N1);
    pairconv16_kernel<27><<<PG, T>>>(RB1_P, 32, T1, w1 + 1 * 6912, T2);

    reduce16_kernel<<<G1, T>>>(T2, N1, bn2g + 16, bn2b + 16, 1.0f / N1, 16);
    bnrelu_self_kernel<<<B1, T>>>(T2, T1, w2 + 1 * 6912 + 13 * 256, X1, 1, N1);
    pairconv16_kernel<27><<<PG, T>>>(RB1_P, 32, T1, w2 + 1 * 6912, X1); // X1 = r1

    reduce16_kernel<<<G1, T>>>(X1, N1, dbng + 16, dbnb + 16, 1.0f / N1, 16);
    bnrelu_zero_kernel<<<B1, T>>>(X1, T1, X2, N1, N2);
    pairconv16_kernel<8><<<PG, T>>>(RB4_P, 128, T1, dw + 1 * 2048, X2); // X2 = z2

    // ---- level 2 ----
    reduce16_kernel<<<G2, T>>>(X2, N2, bn1g + 32, bn1b + 32, 1.0f / N2, 16);
    bnrelu_self_kernel<<<B2, T>>>(X2, T1, w1 + 2 * 6912 + 13 * 256, T2, 0, N2);
    pairconv16_kernel<27><<<PG, T>>>(RB2_P, 64, T1, w1 + 2 * 6912, T2);

    reduce16_kernel<<<G2, T>>>(T2, N2, bn2g + 32, bn2b + 32, 1.0f / N2, 16);
    bnrelu_self_kernel<<<B2, T>>>(T2, T1, w2 + 2 * 6912 + 13 * 256, X2, 1, N2);
    pairconv16_kernel<27><<<PG, T>>>(RB2_P, 64, T1, w2 + 2 * 6912, X2); // X2 = r2

    // ---- join + BN3 + SDF head ----
    reduce_join_kernel<<<G0, T>>>(X0, X1, X2, p01, p12, N0, bn3g, bn3b, 1.0f / N0);
    final_out_kernel<<<B0, T>>>(X0, X1, X2, p01, p12, wsdf, bsdf,
                                (float*)d_out, N0);
}